// round 12
// baseline (speedup 1.0000x reference)
#include <cuda_runtime.h>
#include <cuda_bf16.h>
#include <math.h>
#include <stdint.h>

#define NN 50000
#define EE 500000
#define NP 50048   // NN padded to multiple of 128 for GEMM tiles
#define H 8

// ---------------- scratch (device globals; no runtime allocation) ----------------
__device__ float g_f[4][(size_t)NP * 256];   // per-relation projected source features
__device__ float g_hm[(size_t)NN * 256];     // merchant layer-1 accumulator (fp32)
__device__ float g_el[4][NN * H];
__device__ float g_er[4][NN * H];
__device__ float g_U[2][4][2][256 * H];      // [layer][rel][l/r][c*8+h]
__device__ __align__(16) __nv_bfloat16 g_Ah[2][(size_t)NP * 256];  // A hi (slot0: xm/hm, 1: xt/ht)
__device__ __align__(16) __nv_bfloat16 g_Al[2][(size_t)NP * 256];  // A lo
__device__ __align__(16) __nv_bfloat16 g_Bh16[8][256 * 256];       // W transposed [n][k], hi
__device__ __align__(16) __nv_bfloat16 g_Bl16[8][256 * 256];       // lo
__device__ int   g_rowptr[4][NN + 1];
__device__ int   g_wptr[4][NN];
__device__ int   g_cnt[4][NN];
__device__ int   g_bsum[4][64];
__device__ int   g_col[4][EE];

// ---------------- helpers ----------------
__device__ __forceinline__ uint32_t smem_u32(const void* p) {
    uint32_t a;
    asm("{ .reg .u64 t; cvta.to.shared.u64 t, %1; cvt.u32.u64 %0, t; }" : "=r"(a) : "l"(p));
    return a;
}
__device__ __forceinline__ void cp16(uint32_t saddr, const void* g) {
    asm volatile("cp.async.cg.shared.global [%0], [%1], 16;" :: "r"(saddr), "l"(g) : "memory");
}
__device__ __forceinline__ void ldm_x4(uint32_t* r, uint32_t a) {
    asm volatile("ldmatrix.sync.aligned.m8n8.x4.shared.b16 {%0,%1,%2,%3}, [%4];"
                 : "=r"(r[0]), "=r"(r[1]), "=r"(r[2]), "=r"(r[3]) : "r"(a));
}
__device__ __forceinline__ void ldm_x2(uint32_t* r, uint32_t a) {
    asm volatile("ldmatrix.sync.aligned.m8n8.x2.shared.b16 {%0,%1}, [%2];"
                 : "=r"(r[0]), "=r"(r[1]) : "r"(a));
}
__device__ __forceinline__ void mma_bf16(float* d, const uint32_t* a, const uint32_t* b) {
    asm volatile(
        "mma.sync.aligned.m16n8k16.row.col.f32.bf16.bf16.f32 "
        "{%0,%1,%2,%3}, {%4,%5,%6,%7}, {%8,%9}, {%0,%1,%2,%3};"
        : "+f"(d[0]), "+f"(d[1]), "+f"(d[2]), "+f"(d[3])
        : "r"(a[0]), "r"(a[1]), "r"(a[2]), "r"(a[3]), "r"(b[0]), "r"(b[1]));
}

// ---------------- prep: W transpose+split to bf16 hi/lo, plus U vectors ----------------
__global__ void k_prep_u(const float* __restrict__ W1, const float* __restrict__ a1l,
                         const float* __restrict__ a1r, const float* __restrict__ W2,
                         const float* __restrict__ a2l, const float* __restrict__ a2r) {
    int i = blockIdx.x * 256 + threadIdx.x;
    if (blockIdx.x < 2048) {
        int g = i >> 16;
        int rem = i & 65535;
        int n = rem >> 8;
        int k = rem & 255;
        const float* W = (g >= 4 ? W2 : W1) + (size_t)(g & 3) * 65536;
        float w = W[(size_t)k * 256 + n];
        __nv_bfloat16 hi = __float2bfloat16_rn(w);
        g_Bh16[g][n * 256 + k] = hi;
        g_Bl16[g][n * 256 + k] = __float2bfloat16_rn(w - __bfloat162float(hi));
    } else {
        int j = i - 2048 * 256;
        if (j < 32768) {
            int h = j & 7;
            int c = (j >> 3) & 255;
            int side = (j >> 11) & 1;
            int rel = (j >> 12) & 3;
            int layer = (j >> 14) & 1;
            const float* W = (layer ? W2 : W1) + (size_t)rel * 65536 + (size_t)c * 256 + h * 32;
            const float* a = (layer ? (side ? a2r : a2l) : (side ? a1r : a1l))
                             + (size_t)rel * 256 + h * 32;
            float s = 0.f;
#pragma unroll
            for (int d = 0; d < 32; d++) s += W[d] * a[d];
            g_U[layer][rel][side][c * 8 + h] = s;
        }
    }
}

// ---------------- split X into bf16 hi/lo (warp per row) + fused layer-1 er ----------------
__global__ void k_split(const float* __restrict__ Xin, int slot, int erRel) {
    int w = (blockIdx.x * blockDim.x + threadIdx.x) >> 5;
    if (w >= NP) return;
    int l = threadIdx.x & 31;
    float x[8];
    if (w < NN) {
        float4 v0 = *(const float4*)(Xin + (size_t)w * 256 + l * 8);
        float4 v1 = *(const float4*)(Xin + (size_t)w * 256 + l * 8 + 4);
        x[0] = v0.x; x[1] = v0.y; x[2] = v0.z; x[3] = v0.w;
        x[4] = v1.x; x[5] = v1.y; x[6] = v1.z; x[7] = v1.w;
    } else {
#pragma unroll
        for (int k = 0; k < 8; k++) x[k] = 0.f;
    }
    __align__(16) __nv_bfloat16 hi[8], lo[8];
#pragma unroll
    for (int k = 0; k < 8; k++) {
        hi[k] = __float2bfloat16_rn(x[k]);
        lo[k] = __float2bfloat16_rn(x[k] - __bfloat162float(hi[k]));
    }
    *(uint4*)(&g_Ah[slot][(size_t)w * 256 + l * 8]) = *(uint4*)hi;
    *(uint4*)(&g_Al[slot][(size_t)w * 256 + l * 8]) = *(uint4*)lo;
    if (w < NN) {
        const float* U = g_U[0][erRel][1];
        float er[8] = {0, 0, 0, 0, 0, 0, 0, 0};
#pragma unroll
        for (int k = 0; k < 8; k++) {
            const float* up = U + (l * 8 + k) * 8;
            float xv = x[k];
#pragma unroll
            for (int h = 0; h < 8; h++) er[h] += xv * up[h];
        }
#pragma unroll
        for (int h = 0; h < 8; h++) {
#pragma unroll
            for (int off = 16; off; off >>= 1) er[h] += __shfl_xor_sync(0xffffffffu, er[h], off);
        }
        if (l == 0) {
#pragma unroll
            for (int h = 0; h < 8; h++) g_er[erRel][w * 8 + h] = er[h];
        }
    }
}

// ---------------- init: zero CSR counters ----------------
__global__ void k_zero() {
    int i = blockIdx.x * blockDim.x + threadIdx.x;
    if (i < 4 * NN) ((int*)g_cnt)[i] = 0;
}

// ---------------- CSR build ----------------
__global__ void k_hist(const int* __restrict__ dst) {
    int i = blockIdx.x * blockDim.x + threadIdx.x;
    if (i >= 4 * EE) return;
    int rel = i / EE;
    atomicAdd(&g_cnt[rel][dst[i]], 1);
}

__global__ void k_scan1() {   // grid (49,4) x 1024: block-level inclusive scan
    int rel = blockIdx.y;
    int b = blockIdx.x;
    int tid = threadIdx.x;
    int l = tid & 31, w = tid >> 5;
    int i = b * 1024 + tid;
    int v = (i < NN) ? g_cnt[rel][i] : 0;
    int x = v;
#pragma unroll
    for (int off = 1; off < 32; off <<= 1) {
        int t = __shfl_up_sync(0xffffffffu, x, off);
        if (l >= off) x += t;
    }
    __shared__ int ws[32];
    if (l == 31) ws[w] = x;
    __syncthreads();
    if (w == 0) {
        int y = ws[l];
#pragma unroll
        for (int off = 1; off < 32; off <<= 1) {
            int t = __shfl_up_sync(0xffffffffu, y, off);
            if (l >= off) y += t;
        }
        ws[l] = y;
    }
    __syncthreads();
    int incl = x + (w ? ws[w - 1] : 0);
    if (i < NN) g_wptr[rel][i] = incl;          // temp: inclusive within block
    if (tid == 1023) g_bsum[rel][b] = incl;
}

__global__ void k_scan2() {   // 1 block of 4 threads: scan block sums per relation
    int rel = threadIdx.x;
    if (rel >= 4) return;
    int run = 0;
    for (int b = 0; b < 49; b++) {
        int t = g_bsum[rel][b];
        g_bsum[rel][b] = run;
        run += t;
    }
    g_rowptr[rel][NN] = run;
}

__global__ void k_scan3() {   // apply offsets -> exclusive rowptr/wptr
    int rel = blockIdx.y;
    int b = blockIdx.x;
    int i = b * 1024 + threadIdx.x;
    if (i >= NN) return;
    int excl = g_bsum[rel][b] + g_wptr[rel][i] - g_cnt[rel][i];
    g_rowptr[rel][i] = excl;
    g_wptr[rel][i] = excl;
}

__global__ void k_scatter(const int* __restrict__ src, const int* __restrict__ dst) {
    int i = blockIdx.x * blockDim.x + threadIdx.x;
    if (i >= 4 * EE) return;
    int rel = i / EE;
    int d = dst[i];
    int pos = atomicAdd(&g_wptr[rel][d], 1);
    g_col[rel][pos] = src[i];
}

// ---------------- mma.sync bf16 3-pass GEMM + fused el/er epilogue ----------------
#define AST2 80
#define ABUF2 (128 * AST2)
#define STG2 (4 * ABUF2)
#define GSM2 (2 * STG2)

__device__ __forceinline__ void gemm_issue2(
    char* smbase, int stage, int c, int tid,
    const __nv_bfloat16* __restrict__ Ah, const __nv_bfloat16* __restrict__ Al,
    const __nv_bfloat16* __restrict__ Bh, const __nv_bfloat16* __restrict__ Bl,
    int rowBase, int colBase)
{
    int kb = c * 32;
    uint32_t s = smem_u32(smbase + stage * STG2);
#pragma unroll
    for (int j = 0; j < 8; j++) {
        int mat = j >> 1;
        int idx = ((j & 1) << 8) + tid;   // 0..511
        int r = idx >> 2;
        int q = idx & 3;
        uint32_t so = s + mat * ABUF2 + r * AST2 + q * 16;
        if (mat < 2) {
            size_t go = (size_t)(rowBase + r) * 256 + kb + q * 8;
            cp16(so, (mat == 0 ? Ah : Al) + go);
        } else {
            size_t go = (size_t)(colBase + r) * 256 + kb + q * 8;
            cp16(so, (mat == 2 ? Bh : Bl) + go);
        }
    }
    asm volatile("cp.async.commit_group;" ::: "memory");
}

__global__ void __launch_bounds__(256, 2) k_gemm_mma(
    int layer, const float* __restrict__ alw, const float* __restrict__ arw)
{
    extern __shared__ __align__(128) char sm[];
    const int tid = threadIdx.x;
    const int wid = tid >> 5;
    const int l = tid & 31;
    const int rel = blockIdx.z;
    const int rowBase = blockIdx.x * 128;
    const int colBase = blockIdx.y * 128;
    const int g = layer * 4 + rel;
    const int slot = (rel < 3) ? 0 : 1;

    const __nv_bfloat16* __restrict__ Ah = g_Ah[slot];
    const __nv_bfloat16* __restrict__ Al = g_Al[slot];
    const __nv_bfloat16* __restrict__ Bh = g_Bh16[g];
    const __nv_bfloat16* __restrict__ Bl = g_Bl16[g];
    float* __restrict__ C = g_f[rel];

    const int mBase = (wid & 1) * 64;
    const int nBase = (wid >> 1) * 32;

    float acc[4][4][4];
#pragma unroll
    for (int mt = 0; mt < 4; mt++)
#pragma unroll
        for (int nt = 0; nt < 4; nt++)
#pragma unroll
            for (int q = 0; q < 4; q++) acc[mt][nt][q] = 0.f;

    gemm_issue2(sm, 0, 0, tid, Ah, Al, Bh, Bl, rowBase, colBase);
    gemm_issue2(sm, 1, 1, tid, Ah, Al, Bh, Bl, rowBase, colBase);

    const uint32_t aOff = (mBase + (l & 15)) * AST2 + ((l >> 4) << 4);
    const uint32_t bOff = (nBase + (l & 7)) * AST2 + (((l >> 3) & 1) << 4);

#pragma unroll 1
    for (int c = 0; c < 8; c++) {
        if (c < 7) asm volatile("cp.async.wait_group 1;" ::: "memory");
        else       asm volatile("cp.async.wait_group 0;" ::: "memory");
        __syncthreads();

        uint32_t s = smem_u32(sm + (c & 1) * STG2);
#pragma unroll
        for (int kk = 0; kk < 2; kk++) {
            uint32_t ah[4][4], al2[4][4], bh[4][2], bl[4][2];
#pragma unroll
            for (int mt = 0; mt < 4; mt++) {
                uint32_t a = s + aOff + mt * (16 * AST2) + kk * 32;
                ldm_x4(ah[mt], a);
                ldm_x4(al2[mt], a + ABUF2);
            }
#pragma unroll
            for (int nt = 0; nt < 4; nt++) {
                uint32_t a = s + 2 * ABUF2 + bOff + nt * (8 * AST2) + kk * 32;
                ldm_x2(bh[nt], a);
                ldm_x2(bl[nt], a + ABUF2);
            }
#pragma unroll
            for (int mt = 0; mt < 4; mt++)
#pragma unroll
                for (int nt = 0; nt < 4; nt++) {
                    mma_bf16(acc[mt][nt], ah[mt], bh[nt]);
                    mma_bf16(acc[mt][nt], ah[mt], bl[nt]);
                    mma_bf16(acc[mt][nt], al2[mt], bh[nt]);
                }
        }
        if (c < 6) {
            __syncthreads();
            gemm_issue2(sm, c & 1, c + 2, tid, Ah, Al, Bh, Bl, rowBase, colBase);
        }
    }

    // ---- epilogue 1: write fp32 C tile ----
#pragma unroll
    for (int mt = 0; mt < 4; mt++) {
        int r0 = rowBase + mBase + mt * 16 + (l >> 2);
#pragma unroll
        for (int nt = 0; nt < 4; nt++) {
            int cc = colBase + nBase + nt * 8 + ((l & 3) << 1);
            float* p = C + (size_t)r0 * 256 + cc;
            *(float2*)p = make_float2(acc[mt][nt][0], acc[mt][nt][1]);
            *(float2*)(p + 8 * 256) = make_float2(acc[mt][nt][2], acc[mt][nt][3]);
        }
    }

    // ---- epilogue 2: fused attention projections ----
    // el for all rels (src side); er only for same-type rels 1,2 (dst side)
    {
        const bool wantEr = (rel == 1) || (rel == 2);
        int h = (colBase >> 5) + (wid >> 1);
        const float* alp = alw + rel * 256 + h * 32;
        const float* arp = arw + rel * 256 + h * 32;
        float2 wl[4], wr[4];
#pragma unroll
        for (int nt = 0; nt < 4; nt++) {
            int d = nt * 8 + ((l & 3) << 1);
            wl[nt] = *(const float2*)(alp + d);
            wr[nt] = *(const float2*)(arp + d);
        }
#pragma unroll
        for (int mt = 0; mt < 4; mt++) {
            float elA = 0.f, erA = 0.f, elB = 0.f, erB = 0.f;
#pragma unroll
            for (int nt = 0; nt < 4; nt++) {
                elA += acc[mt][nt][0] * wl[nt].x + acc[mt][nt][1] * wl[nt].y;
                erA += acc[mt][nt][0] * wr[nt].x + acc[mt][nt][1] * wr[nt].y;
                elB += acc[mt][nt][2] * wl[nt].x + acc[mt][nt][3] * wl[nt].y;
                erB += acc[mt][nt][2] * wr[nt].x + acc[mt][nt][3] * wr[nt].y;
            }
#pragma unroll
            for (int off = 1; off <= 2; off <<= 1) {
                elA += __shfl_xor_sync(0xffffffffu, elA, off);
                erA += __shfl_xor_sync(0xffffffffu, erA, off);
                elB += __shfl_xor_sync(0xffffffffu, elB, off);
                erB += __shfl_xor_sync(0xffffffffu, erB, off);
            }
            if ((l & 3) == 0) {
                int rA = rowBase + mBase + mt * 16 + (l >> 2);
                int rB = rA + 8;
                if (rA < NN) {
                    g_el[rel][rA * 8 + h] = elA;
                    if (wantEr) g_er[rel][rA * 8 + h] = erA;
                }
                if (rB < NN) {
                    g_el[rel][rB * 8 + h] = elB;
                    if (wantEr) g_er[rel][rB * 8 + h] = erB;
                }
            }
        }
    }
}

// ---------------- per-relation edge softmax body (warp per dst node) ----------------
__device__ __forceinline__ void agg_one(int rel, int gw, int lane, int h,
                                        const float* __restrict__ bias, float* r) {
    const float* __restrict__ f = g_f[rel];
    const int* __restrict__ col = g_col[rel];
    const float* __restrict__ el = g_el[rel];
    int beg = g_rowptr[rel][gw];
    int end = g_rowptr[rel][gw + 1];
    float erd = g_er[rel][gw * H + h];

    float m = -1e30f;
    for (int j = beg; j < end; j++) {
        int s = col[j];
        float e = el[s * H + h] + erd;
        e = (e > 0.f) ? e : 0.2f * e;
        m = fmaxf(m, e);
    }
    float acc[8];
#pragma unroll
    for (int k = 0; k < 8; k++) acc[k] = 0.f;
    float den = 0.f;
    for (int j = beg; j < end; j++) {
        int s = col[j];
        float e = el[s * H + h] + erd;
        e = (e > 0.f) ? e : 0.2f * e;
        float ex = __expf(e - m);
        den += ex;
        const float4* fp = (const float4*)(f + (size_t)s * 256 + lane * 8);
        float4 v0 = fp[0], v1 = fp[1];
        acc[0] += ex * v0.x; acc[1] += ex * v0.y; acc[2] += ex * v0.z; acc[3] += ex * v0.w;
        acc[4] += ex * v1.x; acc[5] += ex * v1.y; acc[6] += ex * v1.z; acc[7] += ex * v1.w;
    }
    float inv = (den > 0.f) ? 1.f / den : 0.f;
#pragma unroll
    for (int k = 0; k < 8; k++) {
        float v = acc[k] * inv + bias[lane * 8 + k];
        r[k] = (v > 0.f) ? v : expm1f(v);
    }
}

__device__ __forceinline__ void split_store(int slot, int gw, int lane, const float* r) {
    __align__(16) __nv_bfloat16 hi[8], lo[8];
#pragma unroll
    for (int k = 0; k < 8; k++) {
        hi[k] = __float2bfloat16_rn(r[k]);
        lo[k] = __float2bfloat16_rn(r[k] - __bfloat162float(hi[k]));
    }
    *(uint4*)(&g_Ah[slot][(size_t)gw * 256 + lane * 8]) = *(uint4*)hi;
    *(uint4*)(&g_Al[slot][(size_t)gw * 256 + lane * 8]) = *(uint4*)lo;
}

__device__ __forceinline__ void er_fused(int layer, int rel, int gw, int lane, const float* r) {
    const float* U = g_U[layer][rel][1];
    float er[8] = {0, 0, 0, 0, 0, 0, 0, 0};
#pragma unroll
    for (int k = 0; k < 8; k++) {
        const float* up = U + (lane * 8 + k) * 8;
        float xv = r[k];
#pragma unroll
        for (int h = 0; h < 8; h++) er[h] += xv * up[h];
    }
#pragma unroll
    for (int h = 0; h < 8; h++) {
#pragma unroll
        for (int off = 16; off; off >>= 1) er[h] += __shfl_xor_sync(0xffffffffu, er[h], off);
    }
    if (lane == 0) {
#pragma unroll
        for (int h = 0; h < 8; h++) g_er[rel][gw * 8 + h] = er[h];
    }
}

// layer-1 tobacco: rel0 -> split slot1 + er for layer-2 rel0 (dst=ht)
__global__ void k_agg_t(const float* __restrict__ bias) {
    int gw = (blockIdx.x * blockDim.x + threadIdx.x) >> 5;
    if (gw >= NN) return;
    int lane = threadIdx.x & 31;
    int h = lane >> 2;
    float r[8];
    agg_one(0, gw, lane, h, bias, r);
    split_store(1, gw, lane, r);
    er_fused(1, 0, gw, lane, r);
}

// layer-1 merchant, ONE relation per launch (keeps one g_f table hot in L2).
// mode 0: g_hm  = r/3   (rel1)
// mode 1: g_hm += r/3   (rel2)
// mode 2: g_hm += r/3, final -> split slot0 + er for layer-2 rel3 (rel3)
__global__ void k_agg_m(int rel, const float* __restrict__ bias, int mode) {
    int gw = (blockIdx.x * blockDim.x + threadIdx.x) >> 5;
    if (gw >= NN) return;
    int lane = threadIdx.x & 31;
    int h = lane >> 2;
    float r[8];
    agg_one(rel, gw, lane, h, bias, r);
    const float third = 1.f / 3.f;
    float* o = g_hm + (size_t)gw * 256 + lane * 8;
    if (mode == 0) {
        ((float4*)o)[0] = make_float4(r[0] * third, r[1] * third, r[2] * third, r[3] * third);
        ((float4*)o)[1] = make_float4(r[4] * third, r[5] * third, r[6] * third, r[7] * third);
    } else {
        float4 c0 = ((float4*)o)[0], c1 = ((float4*)o)[1];
        c0.x += r[0] * third; c0.y += r[1] * third; c0.z += r[2] * third; c0.w += r[3] * third;
        c1.x += r[4] * third; c1.y += r[5] * third; c1.z += r[6] * third; c1.w += r[7] * third;
        if (mode == 1) {
            ((float4*)o)[0] = c0;
            ((float4*)o)[1] = c1;
        } else {
            float fin[8] = {c0.x, c0.y, c0.z, c0.w, c1.x, c1.y, c1.z, c1.w};
            split_store(0, gw, lane, fin);
            er_fused(1, 3, gw, lane, fin);
        }
    }
}

// layer-2: one relation per launch, write concatenated output + elu
__global__ void k_agg2(int rel, const float* __restrict__ bias, float* __restrict__ out) {
    int gw = (blockIdx.x * blockDim.x + threadIdx.x) >> 5;
    if (gw >= NN) return;
    int lane = threadIdx.x & 31;
    int h = lane >> 2;
    float r[8];
    agg_one(rel, gw, lane, h, bias, r);
    float* o = out + (size_t)gw * 1024 + rel * 256 + lane * 8;
    ((float4*)o)[0] = make_float4(r[0], r[1], r[2], r[3]);
    ((float4*)o)[1] = make_float4(r[4], r[5], r[6], r[7]);
}

// ---------------- launch ----------------
extern "C" void kernel_launch(void* const* d_in, const int* in_sizes, int n_in,
                              void* d_out, int out_size) {
    const float* xm  = (const float*)d_in[0];
    const float* xt  = (const float*)d_in[1];
    const int*   src = (const int*)d_in[2];
    const int*   dst = (const int*)d_in[3];
    const float* W1  = (const float*)d_in[4];
    const float* a1l = (const float*)d_in[5];
    const float* a1r = (const float*)d_in[6];
    const float* b1  = (const float*)d_in[7];
    const float* W2  = (const float*)d_in[8];
    const float* a2l = (const float*)d_in[9];
    const float* a2r = (const float*)d_in[10];
    const float* b2  = (const float*)d_in[11];
    float* out = (float*)d_out;

    cudaFuncSetAttribute(k_gemm_mma, cudaFuncAttributeMaxDynamicSharedMemorySize, GSM2);

    const int SPB = NP / 8;             // k_split: warp per row, 8 rows/block
    dim3 ggrid(NP / 128, 2, 4);
    const int AB = (NN * 32 + 255) / 256;
    dim3 sgrid(49, 4);

    k_prep_u<<<2176, 256>>>(W1, a1l, a1r, W2, a2l, a2r);
    k_split<<<SPB, 256>>>(xm, 0, 3);              // slot0 = xm, er rel3 (dst=xm)
    k_split<<<SPB, 256>>>(xt, 1, 0);              // slot1 = xt, er rel0 (dst=xt)
    k_gemm_mma<<<ggrid, 256, GSM2>>>(0, a1l, a1r);   // <- ncu slot

    k_zero<<<(4 * NN + 255) / 256, 256>>>();
    k_hist<<<(4 * EE + 255) / 256, 256>>>(dst);
    k_scan1<<<sgrid, 1024>>>();
    k_scan2<<<1, 4>>>();
    k_scan3<<<sgrid, 1024>>>();
    k_scatter<<<(4 * EE + 255) / 256, 256>>>(src, dst);

    k_agg_t<<<AB, 256>>>(b1);
    k_agg_m<<<AB, 256>>>(1, b1 + 256, 0);
    k_agg_m<<<AB, 256>>>(2, b1 + 512, 1);
    k_agg_m<<<AB, 256>>>(3, b1 + 768, 2);

    k_gemm_mma<<<ggrid, 256, GSM2>>>(1, a2l, a2r);
    k_agg2<<<AB, 256>>>(0, b2 + 0,   out);
    k_agg2<<<AB, 256>>>(1, b2 + 256, out);
    k_agg2<<<AB, 256>>>(2, b2 + 512, out);
    k_agg2<<<AB, 256>>>(3, b2 + 768, out);
}

// round 15
// speedup vs baseline: 1.9253x; 1.9253x over previous
#include <cuda_runtime.h>
#include <cuda_bf16.h>
#include <math.h>
#include <stdint.h>

#define NN 50000
#define EE 500000
#define NP 50048   // NN padded to multiple of 128 for GEMM tiles
#define H 8

// ---------------- scratch (device globals; no runtime allocation) ----------------
__device__ float g_f[4][(size_t)NP * 256];   // per-relation projected source features
__device__ float g_ht[(size_t)NP * 256];     // layer-1 tobacco features (elu applied)
__device__ float g_hm[(size_t)NP * 256];     // layer-1 merchant features (mean of 3, elu)
__device__ float g_el[4][NN * H];
__device__ float g_er[4][NN * H];
__device__ float g_U[2][4][2][256 * H];
__device__ __align__(16) __nv_bfloat16 g_Ah[2][(size_t)NP * 256];  // A hi (slot0: xm/hm, 1: xt/ht)
__device__ __align__(16) __nv_bfloat16 g_Al[2][(size_t)NP * 256];  // A lo
__device__ __align__(16) __nv_bfloat16 g_Bh16[8][256 * 256];       // W transposed [n][k], hi
__device__ __align__(16) __nv_bfloat16 g_Bl16[8][256 * 256];       // lo
__device__ int   g_rowptr[4][NN + 1];
__device__ int   g_wptr[4][NN];
__device__ int   g_cnt[4][NN];
__device__ int   g_col[4][EE];

// ---------------- helpers ----------------
__device__ __forceinline__ uint32_t smem_u32(const void* p) {
    uint32_t a;
    asm("{ .reg .u64 t; cvta.to.shared.u64 t, %1; cvt.u32.u64 %0, t; }" : "=r"(a) : "l"(p));
    return a;
}
__device__ __forceinline__ void cp16(uint32_t saddr, const void* g) {
    asm volatile("cp.async.cg.shared.global [%0], [%1], 16;" :: "r"(saddr), "l"(g) : "memory");
}
__device__ __forceinline__ void ldm_x4(uint32_t* r, uint32_t a) {
    asm volatile("ldmatrix.sync.aligned.m8n8.x4.shared.b16 {%0,%1,%2,%3}, [%4];"
                 : "=r"(r[0]), "=r"(r[1]), "=r"(r[2]), "=r"(r[3]) : "r"(a));
}
__device__ __forceinline__ void ldm_x2(uint32_t* r, uint32_t a) {
    asm volatile("ldmatrix.sync.aligned.m8n8.x2.shared.b16 {%0,%1}, [%2];"
                 : "=r"(r[0]), "=r"(r[1]) : "r"(a));
}
__device__ __forceinline__ void mma_bf16(float* d, const uint32_t* a, const uint32_t* b) {
    asm volatile(
        "mma.sync.aligned.m16n8k16.row.col.f32.bf16.bf16.f32 "
        "{%0,%1,%2,%3}, {%4,%5,%6,%7}, {%8,%9}, {%0,%1,%2,%3};"
        : "+f"(d[0]), "+f"(d[1]), "+f"(d[2]), "+f"(d[3])
        : "r"(a[0]), "r"(a[1]), "r"(a[2]), "r"(a[3]), "r"(b[0]), "r"(b[1]));
}

// ---------------- init: zero CSR counters ----------------
__global__ void k_zero() {
    int i = blockIdx.x * blockDim.x + threadIdx.x;
    if (i < 4 * NN) ((int*)g_cnt)[i] = 0;
}

// ---------------- CSR build ----------------
__global__ void k_hist(const int* __restrict__ dst) {
    int i = blockIdx.x * blockDim.x + threadIdx.x;
    if (i >= 4 * EE) return;
    int rel = i / EE;
    atomicAdd(&g_cnt[rel][dst[i]], 1);
}

__global__ void k_scan() {   // one block per relation
    int rel = blockIdx.x;
    __shared__ int sh[1024];
    __shared__ int carry_s;
    int tid = threadIdx.x;
    if (tid == 0) carry_s = 0;
    __syncthreads();
    for (int base = 0; base < NN; base += 1024) {
        int i = base + tid;
        int v = (i < NN) ? g_cnt[rel][i] : 0;
        sh[tid] = v;
        __syncthreads();
        for (int off = 1; off < 1024; off <<= 1) {
            int t = (tid >= off) ? sh[tid - off] : 0;
            __syncthreads();
            sh[tid] += t;
            __syncthreads();
        }
        int incl = sh[tid];
        int carry = carry_s;
        if (i < NN) {
            int excl = carry + incl - v;
            g_rowptr[rel][i] = excl;
            g_wptr[rel][i] = excl;
        }
        __syncthreads();
        if (tid == 0) carry_s += sh[1023];
        __syncthreads();
    }
    if (tid == 0) g_rowptr[rel][NN] = carry_s;
}

__global__ void k_scatter(const int* __restrict__ src, const int* __restrict__ dst) {
    int i = blockIdx.x * blockDim.x + threadIdx.x;
    if (i >= 4 * EE) return;
    int rel = i / EE;
    int d = dst[i];
    int pos = atomicAdd(&g_wptr[rel][d], 1);
    g_col[rel][pos] = src[i];
}

// ---------------- U = per-head contraction of W with a ----------------
__global__ void k_u(const float* __restrict__ W1, const float* __restrict__ a1l,
                    const float* __restrict__ a1r, const float* __restrict__ W2,
                    const float* __restrict__ a2l, const float* __restrict__ a2r) {
    int i = blockIdx.x * blockDim.x + threadIdx.x;
    if (i >= 32768) return;
    int h = i & 7;
    int c = (i >> 3) & 255;
    int side = (i >> 11) & 1;
    int rel = (i >> 12) & 3;
    int layer = (i >> 14) & 1;
    const float* W = (layer ? W2 : W1) + (size_t)rel * 65536 + (size_t)c * 256 + h * 32;
    const float* a = (layer ? (side ? a2r : a2l) : (side ? a1r : a1l)) + (size_t)rel * 256 + h * 32;
    float s = 0.f;
#pragma unroll
    for (int d = 0; d < 32; d++) s += W[d] * a[d];
    g_U[layer][rel][side][c * 8 + h] = s;
}

// ---------------- prep: transpose W, split to bf16 hi/lo ----------------
__global__ void k_prep(const float* __restrict__ W1, const float* __restrict__ W2) {
    int i = blockIdx.x * blockDim.x + threadIdx.x;
    if (i >= 8 * 65536) return;
    int g = i >> 16;
    int rem = i & 65535;
    int n = rem >> 8;
    int k = rem & 255;
    const float* W = (g >= 4 ? W2 : W1) + (size_t)(g & 3) * 65536;
    float w = W[(size_t)k * 256 + n];
    __nv_bfloat16 hi = __float2bfloat16_rn(w);
    float lo = w - __bfloat162float(hi);
    g_Bh16[g][n * 256 + k] = hi;
    g_Bl16[g][n * 256 + k] = __float2bfloat16_rn(lo);
}

// ---------------- split A matrices into bf16 hi/lo (zero-pads rows NN..NP) ----------------
__global__ void k_split(const float* __restrict__ Xin, int slot) {
    size_t i = (size_t)blockIdx.x * blockDim.x + threadIdx.x;   // quad index
    if (i >= (size_t)NP * 64) return;
    size_t e = i * 4;
    int row = (int)(e >> 8);
    float4 v = make_float4(0.f, 0.f, 0.f, 0.f);
    if (row < NN) v = *(const float4*)(Xin + e);
    __nv_bfloat16 h0 = __float2bfloat16_rn(v.x), h1 = __float2bfloat16_rn(v.y);
    __nv_bfloat16 h2 = __float2bfloat16_rn(v.z), h3 = __float2bfloat16_rn(v.w);
    __nv_bfloat16 l0 = __float2bfloat16_rn(v.x - __bfloat162float(h0));
    __nv_bfloat16 l1 = __float2bfloat16_rn(v.y - __bfloat162float(h1));
    __nv_bfloat16 l2 = __float2bfloat16_rn(v.z - __bfloat162float(h2));
    __nv_bfloat16 l3 = __float2bfloat16_rn(v.w - __bfloat162float(h3));
    __nv_bfloat162 hh0, hh1, ll0, ll1;
    hh0.x = h0; hh0.y = h1; hh1.x = h2; hh1.y = h3;
    ll0.x = l0; ll0.y = l1; ll1.x = l2; ll1.y = l3;
    *(__nv_bfloat162*)(&g_Ah[slot][e]) = hh0;
    *(__nv_bfloat162*)(&g_Ah[slot][e + 2]) = hh1;
    *(__nv_bfloat162*)(&g_Al[slot][e]) = ll0;
    *(__nv_bfloat162*)(&g_Al[slot][e + 2]) = ll1;
}

// ---------------- mma.sync bf16 3-pass GEMM + fused el/er epilogue ----------------
// CTA tile 128x128, 8 warps of 64x32, K chunked by 32.
// Paired-row smem layout: 2 rows (64B each) packed + 16B pad -> 144B/pair.
//   row_addr(r) = (r>>1)*144 + (r&1)*64   (16B-aligned; 8 consecutive rows hit
//   16B-chunks {0,4,1,5,2,6,3,7} mod 8 -> ldmatrix conflict-free)
// Per-matrix buffer 64*144=9216B; stage = 4 matrices = 36864B; 3 stages = 110592B;
// 2 CTAs/SM (221184 <= 227KB carveout). Single __syncthreads per chunk.
#define PRB   144
#define ABUF3 9216
#define STG3  (4 * ABUF3)     // 36864
#define GSM3  (3 * STG3)      // 110592

__device__ __forceinline__ uint32_t raddr(int r) {
    return (uint32_t)((r >> 1) * PRB + (r & 1) * 64);
}

__device__ __forceinline__ void gemm_issue3(
    char* smbase, int stage, int c, int tid,
    const __nv_bfloat16* __restrict__ Ah, const __nv_bfloat16* __restrict__ Al,
    const __nv_bfloat16* __restrict__ Bh, const __nv_bfloat16* __restrict__ Bl,
    int rowBase, int colBase)
{
    int kb = c * 32;
    uint32_t s = smem_u32(smbase + stage * STG3);
#pragma unroll
    for (int j = 0; j < 8; j++) {
        int mat = j >> 1;
        int idx = ((j & 1) << 8) + tid;   // 0..511
        int r = idx >> 2;                 // 0..127
        int q = idx & 3;                  // 16B chunk within 64B row
        uint32_t so = s + mat * ABUF3 + raddr(r) + q * 16;
        if (mat < 2) {
            size_t go = (size_t)(rowBase + r) * 256 + kb + q * 8;
            cp16(so, (mat == 0 ? Ah : Al) + go);
        } else {
            size_t go = (size_t)(colBase + r) * 256 + kb + q * 8;
            cp16(so, (mat == 2 ? Bh : Bl) + go);
        }
    }
    asm volatile("cp.async.commit_group;" ::: "memory");
}

__global__ void __launch_bounds__(256, 2) k_gemm_mma(
    int layer, const float* __restrict__ alw, const float* __restrict__ arw)
{
    extern __shared__ __align__(128) char sm[];
    const int tid = threadIdx.x;
    const int wid = tid >> 5;
    const int l = tid & 31;
    const int rel = blockIdx.z;
    const int rowBase = blockIdx.x * 128;
    const int colBase = blockIdx.y * 128;
    const int g = layer * 4 + rel;
    const int slot = (rel < 3) ? 0 : 1;

    const __nv_bfloat16* __restrict__ Ah = g_Ah[slot];
    const __nv_bfloat16* __restrict__ Al = g_Al[slot];
    const __nv_bfloat16* __restrict__ Bh = g_Bh16[g];
    const __nv_bfloat16* __restrict__ Bl = g_Bl16[g];
    float* __restrict__ C = g_f[rel];

    const int mBase = (wid & 1) * 64;
    const int nBase = (wid >> 1) * 32;

    float acc[4][4][4];
#pragma unroll
    for (int mt = 0; mt < 4; mt++)
#pragma unroll
        for (int nt = 0; nt < 4; nt++)
#pragma unroll
            for (int q = 0; q < 4; q++) acc[mt][nt][q] = 0.f;

    gemm_issue3(sm, 0, 0, tid, Ah, Al, Bh, Bl, rowBase, colBase);
    gemm_issue3(sm, 1, 1, tid, Ah, Al, Bh, Bl, rowBase, colBase);

    // per-lane ldmatrix offsets (paired-row layout)
    const uint32_t aOff = raddr(mBase + (l & 15)) + ((l >> 4) << 4);
    const uint32_t bOff = raddr(nBase + (l & 7)) + (((l >> 3) & 1) << 4);

#pragma unroll 1
    for (int c = 0; c < 8; c++) {
        if (c < 7) asm volatile("cp.async.wait_group 1;" ::: "memory");
        else       asm volatile("cp.async.wait_group 0;" ::: "memory");
        __syncthreads();
        if (c < 6) {
            int stW = (c + 2) % 3;
            gemm_issue3(sm, stW, c + 2, tid, Ah, Al, Bh, Bl, rowBase, colBase);
        }

        uint32_t s = smem_u32(sm + (c % 3) * STG3);
#pragma unroll
        for (int kk = 0; kk < 2; kk++) {
            uint32_t ah[4][4], al2[4][4], bh[4][2], bl[4][2];
#pragma unroll
            for (int mt = 0; mt < 4; mt++) {
                uint32_t a = s + aOff + mt * (8 * PRB) + kk * 32;   // 16 rows = 8 pairs
                ldm_x4(ah[mt], a);
                ldm_x4(al2[mt], a + ABUF3);
            }
#pragma unroll
            for (int nt = 0; nt < 4; nt++) {
                uint32_t a = s + 2 * ABUF3 + bOff + nt * (4 * PRB) + kk * 32;  // 8 rows = 4 pairs
                ldm_x2(bh[nt], a);
                ldm_x2(bl[nt], a + ABUF3);
            }
#pragma unroll
            for (int mt = 0; mt < 4; mt++)
#pragma unroll
                for (int nt = 0; nt < 4; nt++) {
                    mma_bf16(acc[mt][nt], ah[mt], bh[nt]);
                    mma_bf16(acc[mt][nt], ah[mt], bl[nt]);
                    mma_bf16(acc[mt][nt], al2[mt], bh[nt]);
                }
        }
    }

    // ---- epilogue 1: write fp32 C tile ----
#pragma unroll
    for (int mt = 0; mt < 4; mt++) {
        int r0 = rowBase + mBase + mt * 16 + (l >> 2);
#pragma unroll
        for (int nt = 0; nt < 4; nt++) {
            int cc = colBase + nBase + nt * 8 + ((l & 3) << 1);
            float* p = C + (size_t)r0 * 256 + cc;
            *(float2*)p = make_float2(acc[mt][nt][0], acc[mt][nt][1]);
            *(float2*)(p + 8 * 256) = make_float2(acc[mt][nt][2], acc[mt][nt][3]);
        }
    }

    // ---- epilogue 2: fused attention projections el/er ----
    // this warp's 32 columns = exactly head h
    {
        int h = (colBase >> 5) + (wid >> 1);
        const float* alp = alw + rel * 256 + h * 32;
        const float* arp = arw + rel * 256 + h * 32;
        float2 wl[4], wr[4];
#pragma unroll
        for (int nt = 0; nt < 4; nt++) {
            int d = nt * 8 + ((l & 3) << 1);
            wl[nt] = *(const float2*)(alp + d);
            wr[nt] = *(const float2*)(arp + d);
        }
#pragma unroll
        for (int mt = 0; mt < 4; mt++) {
            float elA = 0.f, erA = 0.f, elB = 0.f, erB = 0.f;
#pragma unroll
            for (int nt = 0; nt < 4; nt++) {
                elA += acc[mt][nt][0] * wl[nt].x + acc[mt][nt][1] * wl[nt].y;
                erA += acc[mt][nt][0] * wr[nt].x + acc[mt][nt][1] * wr[nt].y;
                elB += acc[mt][nt][2] * wl[nt].x + acc[mt][nt][3] * wl[nt].y;
                erB += acc[mt][nt][2] * wr[nt].x + acc[mt][nt][3] * wr[nt].y;
            }
#pragma unroll
            for (int off = 1; off <= 2; off <<= 1) {
                elA += __shfl_xor_sync(0xffffffffu, elA, off);
                erA += __shfl_xor_sync(0xffffffffu, erA, off);
                elB += __shfl_xor_sync(0xffffffffu, elB, off);
                erB += __shfl_xor_sync(0xffffffffu, erB, off);
            }
            if ((l & 3) == 0) {
                int rA = rowBase + mBase + mt * 16 + (l >> 2);
                int rB = rA + 8;
                if (rA < NN) { g_el[rel][rA * 8 + h] = elA; g_er[rel][rA * 8 + h] = erA; }
                if (rB < NN) { g_el[rel][rB * 8 + h] = elB; g_er[rel][rB * 8 + h] = erB; }
            }
        }
    }
}

// ---------------- small projection (only er for rel0/rel3): out[N,8] = X @ U ----------------
__global__ void k_proj(const float* __restrict__ Xin, int xsel, int layer, int rel, int side) {
    const float* __restrict__ X = (xsel == 0) ? Xin : ((xsel == 1) ? g_hm : g_ht);
    __shared__ float sU[256 * 9];
    const float* U = g_U[layer][rel][side];
    for (int i = threadIdx.x; i < 2048; i += blockDim.x) {
        int c = i >> 3, h = i & 7;
        sU[c * 9 + h] = U[i];
    }
    __syncthreads();
    float* out = side ? g_er[rel] : g_el[rel];
    int lane = threadIdx.x & 31;
    int warp = (blockIdx.x * blockDim.x + threadIdx.x) >> 5;
    int nw = (gridDim.x * blockDim.x) >> 5;
    for (int row = warp; row < NN; row += nw) {
        float acc[8] = {0, 0, 0, 0, 0, 0, 0, 0};
#pragma unroll
        for (int i = 0; i < 8; i++) {
            float x = X[(size_t)row * 256 + i * 32 + lane];
            const float* u = &sU[(i * 32 + lane) * 9];
#pragma unroll
            for (int h = 0; h < 8; h++) acc[h] += x * u[h];
        }
#pragma unroll
        for (int h = 0; h < 8; h++) {
#pragma unroll
            for (int off = 16; off; off >>= 1) acc[h] += __shfl_xor_sync(0xffffffffu, acc[h], off);
        }
        if (lane == 0) {
#pragma unroll
            for (int h = 0; h < 8; h++) out[(size_t)row * 8 + h] = acc[h];
        }
    }
}

// ---------------- GAT edge softmax + aggregation (warp per dst node) ----------------
// mode 0: store elu -> g_ht AND bf16 hi/lo split to slot 1   (layer1 rel0)
// mode 1: g_hm  = elu/3                                      (layer1 rel1)
// mode 2: g_hm += elu/3                                      (layer1 rel2)
// mode 3: g_hm += elu/3, store final, split to slot 0        (layer1 rel3)
// mode 4: store elu -> out_ext (stride 1024)                 (layer2)
__global__ void k_agg(int rel, const float* __restrict__ bias,
                      float* __restrict__ out_ext, int mode) {
    int gw = (blockIdx.x * blockDim.x + threadIdx.x) >> 5;
    if (gw >= NN) return;
    int lane = threadIdx.x & 31;
    int h = lane >> 2;
    const float* __restrict__ f = g_f[rel];
    const int* __restrict__ col = g_col[rel];
    const float* __restrict__ el = g_el[rel];
    int beg = g_rowptr[rel][gw];
    int end = g_rowptr[rel][gw + 1];
    float erd = g_er[rel][gw * H + h];

    float m = -1e30f;
    for (int j = beg; j < end; j++) {
        int s = col[j];
        float e = el[s * H + h] + erd;
        e = (e > 0.f) ? e : 0.2f * e;
        m = fmaxf(m, e);
    }
    float acc[8];
#pragma unroll
    for (int k = 0; k < 8; k++) acc[k] = 0.f;
    float den = 0.f;
    for (int j = beg; j < end; j++) {
        int s = col[j];
        float e = el[s * H + h] + erd;
        e = (e > 0.f) ? e : 0.2f * e;
        float ex = __expf(e - m);
        den += ex;
        const float4* fp = (const float4*)(f + (size_t)s * 256 + lane * 8);
        float4 v0 = fp[0], v1 = fp[1];
        acc[0] += ex * v0.x; acc[1] += ex * v0.y; acc[2] += ex * v0.z; acc[3] += ex * v0.w;
        acc[4] += ex * v1.x; acc[5] += ex * v1.y; acc[6] += ex * v1.z; acc[7] += ex * v1.w;
    }
    float inv = (den > 0.f) ? 1.f / den : 0.f;
    float r[8];
#pragma unroll
    for (int k = 0; k < 8; k++) {
        float v = acc[k] * inv + bias[lane * 8 + k];
        r[k] = (v > 0.f) ? v : expm1f(v);
    }
    if (mode == 0) {
        float* o = g_ht + (size_t)gw * 256 + lane * 8;
        ((float4*)o)[0] = make_float4(r[0], r[1], r[2], r[3]);
        ((float4*)o)[1] = make_float4(r[4], r[5], r[6], r[7]);
        __align__(16) __nv_bfloat16 hi[8], lo[8];
#pragma unroll
        for (int k = 0; k < 8; k++) {
            hi[k] = __float2bfloat16_rn(r[k]);
            lo[k] = __float2bfloat16_rn(r[k] - __bfloat162float(hi[k]));
        }
        *(uint4*)(&g_Ah[1][(size_t)gw * 256 + lane * 8]) = *(uint4*)hi;
        *(uint4*)(&g_Al[1][(size_t)gw * 256 + lane * 8]) = *(uint4*)lo;
    } else if (mode == 1) {
        float* o = g_hm + (size_t)gw * 256 + lane * 8;
        const float third = 1.f / 3.f;
        ((float4*)o)[0] = make_float4(r[0] * third, r[1] * third, r[2] * third, r[3] * third);
        ((float4*)o)[1] = make_float4(r[4] * third, r[5] * third, r[6] * third, r[7] * third);
    } else if (mode == 2 || mode == 3) {
        float* o = g_hm + (size_t)gw * 256 + lane * 8;
        float4 c0 = ((float4*)o)[0], c1 = ((float4*)o)[1];
        const float third = 1.f / 3.f;
        c0.x += r[0] * third; c0.y += r[1] * third; c0.z += r[2] * third; c0.w += r[3] * third;
        c1.x += r[4] * third; c1.y += r[5] * third; c1.z += r[6] * third; c1.w += r[7] * third;
        ((float4*)o)[0] = c0;
        ((float4*)o)[1] = c1;
        if (mode == 3) {
            float fin[8] = {c0.x, c0.y, c0.z, c0.w, c1.x, c1.y, c1.z, c1.w};
            __align__(16) __nv_bfloat16 hi[8], lo[8];
#pragma unroll
            for (int k = 0; k < 8; k++) {
                hi[k] = __float2bfloat16_rn(fin[k]);
                lo[k] = __float2bfloat16_rn(fin[k] - __bfloat162float(hi[k]));
            }
            *(uint4*)(&g_Ah[0][(size_t)gw * 256 + lane * 8]) = *(uint4*)hi;
            *(uint4*)(&g_Al[0][(size_t)gw * 256 + lane * 8]) = *(uint4*)lo;
        }
    } else {
        float* o = out_ext + (size_t)gw * 1024 + lane * 8;
        ((float4*)o)[0] = make_float4(r[0], r[1], r[2], r[3]);
        ((float4*)o)[1] = make_float4(r[4], r[5], r[6], r[7]);
    }
}

// ---------------- launch ----------------
extern "C" void kernel_launch(void* const* d_in, const int* in_sizes, int n_in,
                              void* d_out, int out_size) {
    const float* xm  = (const float*)d_in[0];
    const float* xt  = (const float*)d_in[1];
    const int*   src = (const int*)d_in[2];
    const int*   dst = (const int*)d_in[3];
    const float* W1  = (const float*)d_in[4];
    const float* a1l = (const float*)d_in[5];
    const float* a1r = (const float*)d_in[6];
    const float* b1  = (const float*)d_in[7];
    const float* W2  = (const float*)d_in[8];
    const float* a2l = (const float*)d_in[9];
    const float* a2r = (const float*)d_in[10];
    const float* b2  = (const float*)d_in[11];
    float* out = (float*)d_out;

    cudaFuncSetAttribute(k_gemm_mma, cudaFuncAttributeMaxDynamicSharedMemorySize, GSM3);

    const int SB = (NP * 64 + 255) / 256;
    dim3 ggrid(NP / 128, 2, 4);
    const int PB = 1600;
    const int AB = (NN * 32 + 255) / 256;

    // GEMM placed at the profiled launch slot (4th kernel)
    k_prep<<<2048, 256>>>(W1, W2);
    k_split<<<SB, 256>>>(xm, 0);
    k_split<<<SB, 256>>>(xt, 1);
    k_gemm_mma<<<ggrid, 256, GSM3>>>(0, a1l, a1r);     // <- ncu slot

    k_zero<<<(4 * NN + 255) / 256, 256>>>();
    k_hist<<<(4 * EE + 255) / 256, 256>>>(dst);
    k_scan<<<4, 1024>>>();
    k_scatter<<<(4 * EE + 255) / 256, 256>>>(src, dst);
    k_u<<<128, 256>>>(W1, a1l, a1r, W2, a2l, a2r);

    // fix er for cross-type relations (dst type != src type)
    k_proj<<<PB, 256>>>(xt, 0, 0, 0, 1);   // er rel0: dst=xt
    k_proj<<<PB, 256>>>(xm, 0, 0, 3, 1);   // er rel3: dst=xm

    k_agg<<<AB, 256>>>(0, b1 + 0,   nullptr, 0);   // ht + split slot1
    k_agg<<<AB, 256>>>(1, b1 + 256, nullptr, 1);   // hm  = elu/3
    k_agg<<<AB, 256>>>(2, b1 + 512, nullptr, 2);   // hm += elu/3
    k_agg<<<AB, 256>>>(3, b1 + 768, nullptr, 3);   // hm += elu/3 + split slot0

    // ---- layer 2 ----
    k_gemm_mma<<<ggrid, 256, GSM3>>>(1, a2l, a2r);
    k_proj<<<PB, 256>>>(nullptr, 2, 1, 0, 1);  // er rel0: dst=ht
    k_proj<<<PB, 256>>>(nullptr, 1, 1, 3, 1);  // er rel3: dst=hm
    k_agg<<<AB, 256>>>(0, b2 + 0,   out + 0,   4);
    k_agg<<<AB, 256>>>(1, b2 + 256, out + 256, 4);
    k_agg<<<AB, 256>>>(2, b2 + 512, out + 512, 4);
    k_agg<<<AB, 256>>>(3, b2 + 768, out + 768, 4);
}

// round 16
// speedup vs baseline: 2.0573x; 1.0686x over previous
#include <cuda_runtime.h>
#include <cuda_bf16.h>
#include <cuda_fp16.h>
#include <math.h>
#include <stdint.h>

#define NN 50000
#define EE 500000
#define NP 50048   // NN padded to multiple of 128 for GEMM tiles
#define H 8

// ---------------- scratch (device globals; no runtime allocation) ----------------
__device__ __align__(16) __half g_f[4][(size_t)NP * 256];  // per-relation projected features (fp16)
__device__ float g_ht[(size_t)NP * 256];     // layer-1 tobacco features (elu applied)
__device__ float g_hm[(size_t)NP * 256];     // layer-1 merchant features (mean of 3, elu)
__device__ float g_el[4][NN * H];
__device__ float g_er[4][NN * H];
__device__ float g_U[2][4][2][256 * H];
__device__ __align__(16) __nv_bfloat16 g_Ah[2][(size_t)NP * 256];  // A hi (slot0: xm/hm, 1: xt/ht)
__device__ __align__(16) __nv_bfloat16 g_Al[2][(size_t)NP * 256];  // A lo
__device__ __align__(16) __nv_bfloat16 g_Bh16[8][256 * 256];       // W transposed [n][k], hi
__device__ __align__(16) __nv_bfloat16 g_Bl16[8][256 * 256];       // lo
__device__ int   g_rowptr[4][NN + 1];
__device__ int   g_wptr[4][NN];
__device__ int   g_cnt[4][NN];
__device__ int   g_col[4][EE];

// ---------------- helpers ----------------
__device__ __forceinline__ uint32_t smem_u32(const void* p) {
    uint32_t a;
    asm("{ .reg .u64 t; cvta.to.shared.u64 t, %1; cvt.u32.u64 %0, t; }" : "=r"(a) : "l"(p));
    return a;
}
__device__ __forceinline__ void cp16(uint32_t saddr, const void* g) {
    asm volatile("cp.async.cg.shared.global [%0], [%1], 16;" :: "r"(saddr), "l"(g) : "memory");
}
__device__ __forceinline__ void ldm_x4(uint32_t* r, uint32_t a) {
    asm volatile("ldmatrix.sync.aligned.m8n8.x4.shared.b16 {%0,%1,%2,%3}, [%4];"
                 : "=r"(r[0]), "=r"(r[1]), "=r"(r[2]), "=r"(r[3]) : "r"(a));
}
__device__ __forceinline__ void ldm_x2(uint32_t* r, uint32_t a) {
    asm volatile("ldmatrix.sync.aligned.m8n8.x2.shared.b16 {%0,%1}, [%2];"
                 : "=r"(r[0]), "=r"(r[1]) : "r"(a));
}
__device__ __forceinline__ void mma_bf16(float* d, const uint32_t* a, const uint32_t* b) {
    asm volatile(
        "mma.sync.aligned.m16n8k16.row.col.f32.bf16.bf16.f32 "
        "{%0,%1,%2,%3}, {%4,%5,%6,%7}, {%8,%9}, {%0,%1,%2,%3};"
        : "+f"(d[0]), "+f"(d[1]), "+f"(d[2]), "+f"(d[3])
        : "r"(a[0]), "r"(a[1]), "r"(a[2]), "r"(a[3]), "r"(b[0]), "r"(b[1]));
}

// ---------------- init: zero CSR counters ----------------
__global__ void k_zero() {
    int i = blockIdx.x * blockDim.x + threadIdx.x;
    if (i < 4 * NN) ((int*)g_cnt)[i] = 0;
}

// ---------------- CSR build ----------------
__global__ void k_hist(const int* __restrict__ dst) {
    int i = blockIdx.x * blockDim.x + threadIdx.x;
    if (i >= 4 * EE) return;
    int rel = i / EE;
    atomicAdd(&g_cnt[rel][dst[i]], 1);
}

__global__ void k_scan() {   // one block per relation
    int rel = blockIdx.x;
    __shared__ int sh[1024];
    __shared__ int carry_s;
    int tid = threadIdx.x;
    if (tid == 0) carry_s = 0;
    __syncthreads();
    for (int base = 0; base < NN; base += 1024) {
        int i = base + tid;
        int v = (i < NN) ? g_cnt[rel][i] : 0;
        sh[tid] = v;
        __syncthreads();
        for (int off = 1; off < 1024; off <<= 1) {
            int t = (tid >= off) ? sh[tid - off] : 0;
            __syncthreads();
            sh[tid] += t;
            __syncthreads();
        }
        int incl = sh[tid];
        int carry = carry_s;
        if (i < NN) {
            int excl = carry + incl - v;
            g_rowptr[rel][i] = excl;
            g_wptr[rel][i] = excl;
        }
        __syncthreads();
        if (tid == 0) carry_s += sh[1023];
        __syncthreads();
    }
    if (tid == 0) g_rowptr[rel][NN] = carry_s;
}

__global__ void k_scatter(const int* __restrict__ src, const int* __restrict__ dst) {
    int i = blockIdx.x * blockDim.x + threadIdx.x;
    if (i >= 4 * EE) return;
    int rel = i / EE;
    int d = dst[i];
    int pos = atomicAdd(&g_wptr[rel][d], 1);
    g_col[rel][pos] = src[i];
}

// ---------------- U = per-head contraction of W with a ----------------
__global__ void k_u(const float* __restrict__ W1, const float* __restrict__ a1l,
                    const float* __restrict__ a1r, const float* __restrict__ W2,
                    const float* __restrict__ a2l, const float* __restrict__ a2r) {
    int i = blockIdx.x * blockDim.x + threadIdx.x;
    if (i >= 32768) return;
    int h = i & 7;
    int c = (i >> 3) & 255;
    int side = (i >> 11) & 1;
    int rel = (i >> 12) & 3;
    int layer = (i >> 14) & 1;
    const float* W = (layer ? W2 : W1) + (size_t)rel * 65536 + (size_t)c * 256 + h * 32;
    const float* a = (layer ? (side ? a2r : a2l) : (side ? a1r : a1l)) + (size_t)rel * 256 + h * 32;
    float s = 0.f;
#pragma unroll
    for (int d = 0; d < 32; d++) s += W[d] * a[d];
    g_U[layer][rel][side][c * 8 + h] = s;
}

// ---------------- prep: transpose W, split to bf16 hi/lo ----------------
__global__ void k_prep(const float* __restrict__ W1, const float* __restrict__ W2) {
    int i = blockIdx.x * blockDim.x + threadIdx.x;
    if (i >= 8 * 65536) return;
    int g = i >> 16;
    int rem = i & 65535;
    int n = rem >> 8;
    int k = rem & 255;
    const float* W = (g >= 4 ? W2 : W1) + (size_t)(g & 3) * 65536;
    float w = W[(size_t)k * 256 + n];
    __nv_bfloat16 hi = __float2bfloat16_rn(w);
    float lo = w - __bfloat162float(hi);
    g_Bh16[g][n * 256 + k] = hi;
    g_Bl16[g][n * 256 + k] = __float2bfloat16_rn(lo);
}

// ---------------- split A matrices into bf16 hi/lo (zero-pads rows NN..NP) ----------------
__global__ void k_split(const float* __restrict__ Xin, int slot) {
    size_t i = (size_t)blockIdx.x * blockDim.x + threadIdx.x;   // quad index
    if (i >= (size_t)NP * 64) return;
    size_t e = i * 4;
    int row = (int)(e >> 8);
    float4 v = make_float4(0.f, 0.f, 0.f, 0.f);
    if (row < NN) v = *(const float4*)(Xin + e);
    __nv_bfloat16 h0 = __float2bfloat16_rn(v.x), h1 = __float2bfloat16_rn(v.y);
    __nv_bfloat16 h2 = __float2bfloat16_rn(v.z), h3 = __float2bfloat16_rn(v.w);
    __nv_bfloat16 l0 = __float2bfloat16_rn(v.x - __bfloat162float(h0));
    __nv_bfloat16 l1 = __float2bfloat16_rn(v.y - __bfloat162float(h1));
    __nv_bfloat16 l2 = __float2bfloat16_rn(v.z - __bfloat162float(h2));
    __nv_bfloat16 l3 = __float2bfloat16_rn(v.w - __bfloat162float(h3));
    __nv_bfloat162 hh0, hh1, ll0, ll1;
    hh0.x = h0; hh0.y = h1; hh1.x = h2; hh1.y = h3;
    ll0.x = l0; ll0.y = l1; ll1.x = l2; ll1.y = l3;
    *(__nv_bfloat162*)(&g_Ah[slot][e]) = hh0;
    *(__nv_bfloat162*)(&g_Ah[slot][e + 2]) = hh1;
    *(__nv_bfloat162*)(&g_Al[slot][e]) = ll0;
    *(__nv_bfloat162*)(&g_Al[slot][e + 2]) = ll1;
}

// ---------------- mma.sync bf16 3-pass GEMM + fused el/er epilogue ----------------
// CTA tile 128x128, 8 warps of 64x32, K chunked by 32, paired-row smem layout,
// 3 stages, 2 CTAs/SM, single __syncthreads per chunk. (Identical to R14.)
#define PRB   144
#define ABUF3 9216
#define STG3  (4 * ABUF3)     // 36864
#define GSM3  (3 * STG3)      // 110592

__device__ __forceinline__ uint32_t raddr(int r) {
    return (uint32_t)((r >> 1) * PRB + (r & 1) * 64);
}

__device__ __forceinline__ void gemm_issue3(
    char* smbase, int stage, int c, int tid,
    const __nv_bfloat16* __restrict__ Ah, const __nv_bfloat16* __restrict__ Al,
    const __nv_bfloat16* __restrict__ Bh, const __nv_bfloat16* __restrict__ Bl,
    int rowBase, int colBase)
{
    int kb = c * 32;
    uint32_t s = smem_u32(smbase + stage * STG3);
#pragma unroll
    for (int j = 0; j < 8; j++) {
        int mat = j >> 1;
        int idx = ((j & 1) << 8) + tid;   // 0..511
        int r = idx >> 2;                 // 0..127
        int q = idx & 3;                  // 16B chunk within 64B row
        uint32_t so = s + mat * ABUF3 + raddr(r) + q * 16;
        if (mat < 2) {
            size_t go = (size_t)(rowBase + r) * 256 + kb + q * 8;
            cp16(so, (mat == 0 ? Ah : Al) + go);
        } else {
            size_t go = (size_t)(colBase + r) * 256 + kb + q * 8;
            cp16(so, (mat == 2 ? Bh : Bl) + go);
        }
    }
    asm volatile("cp.async.commit_group;" ::: "memory");
}

__global__ void __launch_bounds__(256, 2) k_gemm_mma(
    int layer, const float* __restrict__ alw, const float* __restrict__ arw)
{
    extern __shared__ __align__(128) char sm[];
    const int tid = threadIdx.x;
    const int wid = tid >> 5;
    const int l = tid & 31;
    const int rel = blockIdx.z;
    const int rowBase = blockIdx.x * 128;
    const int colBase = blockIdx.y * 128;
    const int g = layer * 4 + rel;
    const int slot = (rel < 3) ? 0 : 1;

    const __nv_bfloat16* __restrict__ Ah = g_Ah[slot];
    const __nv_bfloat16* __restrict__ Al = g_Al[slot];
    const __nv_bfloat16* __restrict__ Bh = g_Bh16[g];
    const __nv_bfloat16* __restrict__ Bl = g_Bl16[g];
    __half* __restrict__ C = g_f[rel];

    const int mBase = (wid & 1) * 64;
    const int nBase = (wid >> 1) * 32;

    float acc[4][4][4];
#pragma unroll
    for (int mt = 0; mt < 4; mt++)
#pragma unroll
        for (int nt = 0; nt < 4; nt++)
#pragma unroll
            for (int q = 0; q < 4; q++) acc[mt][nt][q] = 0.f;

    gemm_issue3(sm, 0, 0, tid, Ah, Al, Bh, Bl, rowBase, colBase);
    gemm_issue3(sm, 1, 1, tid, Ah, Al, Bh, Bl, rowBase, colBase);

    // per-lane ldmatrix offsets (paired-row layout)
    const uint32_t aOff = raddr(mBase + (l & 15)) + ((l >> 4) << 4);
    const uint32_t bOff = raddr(nBase + (l & 7)) + (((l >> 3) & 1) << 4);

#pragma unroll 1
    for (int c = 0; c < 8; c++) {
        if (c < 7) asm volatile("cp.async.wait_group 1;" ::: "memory");
        else       asm volatile("cp.async.wait_group 0;" ::: "memory");
        __syncthreads();
        if (c < 6) {
            int stW = (c + 2) % 3;
            gemm_issue3(sm, stW, c + 2, tid, Ah, Al, Bh, Bl, rowBase, colBase);
        }

        uint32_t s = smem_u32(sm + (c % 3) * STG3);
#pragma unroll
        for (int kk = 0; kk < 2; kk++) {
            uint32_t ah[4][4], al2[4][4], bh[4][2], bl[4][2];
#pragma unroll
            for (int mt = 0; mt < 4; mt++) {
                uint32_t a = s + aOff + mt * (8 * PRB) + kk * 32;   // 16 rows = 8 pairs
                ldm_x4(ah[mt], a);
                ldm_x4(al2[mt], a + ABUF3);
            }
#pragma unroll
            for (int nt = 0; nt < 4; nt++) {
                uint32_t a = s + 2 * ABUF3 + bOff + nt * (4 * PRB) + kk * 32;  // 8 rows = 4 pairs
                ldm_x2(bh[nt], a);
                ldm_x2(bl[nt], a + ABUF3);
            }
#pragma unroll
            for (int mt = 0; mt < 4; mt++)
#pragma unroll
                for (int nt = 0; nt < 4; nt++) {
                    mma_bf16(acc[mt][nt], ah[mt], bh[nt]);
                    mma_bf16(acc[mt][nt], ah[mt], bl[nt]);
                    mma_bf16(acc[mt][nt], al2[mt], bh[nt]);
                }
        }
    }

    // ---- epilogue 1: write fp16 C tile ----
#pragma unroll
    for (int mt = 0; mt < 4; mt++) {
        int r0 = rowBase + mBase + mt * 16 + (l >> 2);
#pragma unroll
        for (int nt = 0; nt < 4; nt++) {
            int cc = colBase + nBase + nt * 8 + ((l & 3) << 1);
            __half* p = C + (size_t)r0 * 256 + cc;
            *(__half2*)p = __floats2half2_rn(acc[mt][nt][0], acc[mt][nt][1]);
            *(__half2*)(p + 8 * 256) = __floats2half2_rn(acc[mt][nt][2], acc[mt][nt][3]);
        }
    }

    // ---- epilogue 2: fused attention projections el/er (fp32 accumulators) ----
    {
        int h = (colBase >> 5) + (wid >> 1);
        const float* alp = alw + rel * 256 + h * 32;
        const float* arp = arw + rel * 256 + h * 32;
        float2 wl[4], wr[4];
#pragma unroll
        for (int nt = 0; nt < 4; nt++) {
            int d = nt * 8 + ((l & 3) << 1);
            wl[nt] = *(const float2*)(alp + d);
            wr[nt] = *(const float2*)(arp + d);
        }
#pragma unroll
        for (int mt = 0; mt < 4; mt++) {
            float elA = 0.f, erA = 0.f, elB = 0.f, erB = 0.f;
#pragma unroll
            for (int nt = 0; nt < 4; nt++) {
                elA += acc[mt][nt][0] * wl[nt].x + acc[mt][nt][1] * wl[nt].y;
                erA += acc[mt][nt][0] * wr[nt].x + acc[mt][nt][1] * wr[nt].y;
                elB += acc[mt][nt][2] * wl[nt].x + acc[mt][nt][3] * wl[nt].y;
                erB += acc[mt][nt][2] * wr[nt].x + acc[mt][nt][3] * wr[nt].y;
            }
#pragma unroll
            for (int off = 1; off <= 2; off <<= 1) {
                elA += __shfl_xor_sync(0xffffffffu, elA, off);
                erA += __shfl_xor_sync(0xffffffffu, erA, off);
                elB += __shfl_xor_sync(0xffffffffu, elB, off);
                erB += __shfl_xor_sync(0xffffffffu, erB, off);
            }
            if ((l & 3) == 0) {
                int rA = rowBase + mBase + mt * 16 + (l >> 2);
                int rB = rA + 8;
                if (rA < NN) { g_el[rel][rA * 8 + h] = elA; g_er[rel][rA * 8 + h] = erA; }
                if (rB < NN) { g_el[rel][rB * 8 + h] = elB; g_er[rel][rB * 8 + h] = erB; }
            }
        }
    }
}

// ---------------- small projection (only er for rel0/rel3): out[N,8] = X @ U ----------------
__global__ void k_proj(const float* __restrict__ Xin, int xsel, int layer, int rel, int side) {
    const float* __restrict__ X = (xsel == 0) ? Xin : ((xsel == 1) ? g_hm : g_ht);
    __shared__ float sU[256 * 9];
    const float* U = g_U[layer][rel][side];
    for (int i = threadIdx.x; i < 2048; i += blockDim.x) {
        int c = i >> 3, h = i & 7;
        sU[c * 9 + h] = U[i];
    }
    __syncthreads();
    float* out = side ? g_er[rel] : g_el[rel];
    int lane = threadIdx.x & 31;
    int warp = (blockIdx.x * blockDim.x + threadIdx.x) >> 5;
    int nw = (gridDim.x * blockDim.x) >> 5;
    for (int row = warp; row < NN; row += nw) {
        float acc[8] = {0, 0, 0, 0, 0, 0, 0, 0};
#pragma unroll
        for (int i = 0; i < 8; i++) {
            float x = X[(size_t)row * 256 + i * 32 + lane];
            const float* u = &sU[(i * 32 + lane) * 9];
#pragma unroll
            for (int h = 0; h < 8; h++) acc[h] += x * u[h];
        }
#pragma unroll
        for (int h = 0; h < 8; h++) {
#pragma unroll
            for (int off = 16; off; off >>= 1) acc[h] += __shfl_xor_sync(0xffffffffu, acc[h], off);
        }
        if (lane == 0) {
#pragma unroll
            for (int h = 0; h < 8; h++) out[(size_t)row * 8 + h] = acc[h];
        }
    }
}

// ---------------- GAT edge softmax + aggregation (warp per dst node) ----------------
// mode 0: store elu -> g_ht AND bf16 hi/lo split to slot 1   (layer1 rel0)
// mode 1: g_hm  = elu/3                                      (layer1 rel1)
// mode 2: g_hm += elu/3                                      (layer1 rel2)
// mode 3: g_hm += elu/3, store final, split to slot 0        (layer1 rel3)
// mode 4: store elu -> out_ext (stride 1024)                 (layer2)
__global__ void k_agg(int rel, const float* __restrict__ bias,
                      float* __restrict__ out_ext, int mode) {
    int gw = (blockIdx.x * blockDim.x + threadIdx.x) >> 5;
    if (gw >= NN) return;
    int lane = threadIdx.x & 31;
    int h = lane >> 2;
    const __half* __restrict__ f = g_f[rel];
    const int* __restrict__ col = g_col[rel];
    const float* __restrict__ el = g_el[rel];
    int beg = g_rowptr[rel][gw];
    int end = g_rowptr[rel][gw + 1];
    float erd = g_er[rel][gw * H + h];

    float m = -1e30f;
    for (int j = beg; j < end; j++) {
        int s = col[j];
        float e = el[s * H + h] + erd;
        e = (e > 0.f) ? e : 0.2f * e;
        m = fmaxf(m, e);
    }
    float acc[8];
#pragma unroll
    for (int k = 0; k < 8; k++) acc[k] = 0.f;
    float den = 0.f;
    for (int j = beg; j < end; j++) {
        int s = col[j];
        float e = el[s * H + h] + erd;
        e = (e > 0.f) ? e : 0.2f * e;
        float ex = __expf(e - m);
        den += ex;
        uint4 raw = *(const uint4*)(f + (size_t)s * 256 + lane * 8);
        float2 f0 = __half22float2(*(__half2*)&raw.x);
        float2 f1 = __half22float2(*(__half2*)&raw.y);
        float2 f2 = __half22float2(*(__half2*)&raw.z);
        float2 f3 = __half22float2(*(__half2*)&raw.w);
        acc[0] += ex * f0.x; acc[1] += ex * f0.y; acc[2] += ex * f1.x; acc[3] += ex * f1.y;
        acc[4] += ex * f2.x; acc[5] += ex * f2.y; acc[6] += ex * f3.x; acc[7] += ex * f3.y;
    }
    float inv = (den > 0.f) ? 1.f / den : 0.f;
    float r[8];
#pragma unroll
    for (int k = 0; k < 8; k++) {
        float v = acc[k] * inv + bias[lane * 8 + k];
        r[k] = (v > 0.f) ? v : expm1f(v);
    }
    if (mode == 0) {
        float* o = g_ht + (size_t)gw * 256 + lane * 8;
        ((float4*)o)[0] = make_float4(r[0], r[1], r[2], r[3]);
        ((float4*)o)[1] = make_float4(r[4], r[5], r[6], r[7]);
        __align__(16) __nv_bfloat16 hi[8], lo[8];
#pragma unroll
        for (int k = 0; k < 8; k++) {
            hi[k] = __float2bfloat16_rn(r[k]);
            lo[k] = __float2bfloat16_rn(r[k] - __bfloat162float(hi[k]));
        }
        *(uint4*)(&g_Ah[1][(size_t)gw * 256 + lane * 8]) = *(uint4*)hi;
        *(uint4*)(&g_Al[1][(size_t)gw * 256 + lane * 8]) = *(uint4*)lo;
    } else if (mode == 1) {
        float* o = g_hm + (size_t)gw * 256 + lane * 8;
        const float third = 1.f / 3.f;
        ((float4*)o)[0] = make_float4(r[0] * third, r[1] * third, r[2] * third, r[3] * third);
        ((float4*)o)[1] = make_float4(r[4] * third, r[5] * third, r[6] * third, r[7] * third);
    } else if (mode == 2 || mode == 3) {
        float* o = g_hm + (size_t)gw * 256 + lane * 8;
        float4 c0 = ((float4*)o)[0], c1 = ((float4*)o)[1];
        const float third = 1.f / 3.f;
        c0.x += r[0] * third; c0.y += r[1] * third; c0.z += r[2] * third; c0.w += r[3] * third;
        c1.x += r[4] * third; c1.y += r[5] * third; c1.z += r[6] * third; c1.w += r[7] * third;
        ((float4*)o)[0] = c0;
        ((float4*)o)[1] = c1;
        if (mode == 3) {
            float fin[8] = {c0.x, c0.y, c0.z, c0.w, c1.x, c1.y, c1.z, c1.w};
            __align__(16) __nv_bfloat16 hi[8], lo[8];
#pragma unroll
            for (int k = 0; k < 8; k++) {
                hi[k] = __float2bfloat16_rn(fin[k]);
                lo[k] = __float2bfloat16_rn(fin[k] - __bfloat162float(hi[k]));
            }
            *(uint4*)(&g_Ah[0][(size_t)gw * 256 + lane * 8]) = *(uint4*)hi;
            *(uint4*)(&g_Al[0][(size_t)gw * 256 + lane * 8]) = *(uint4*)lo;
        }
    } else {
        float* o = out_ext + (size_t)gw * 1024 + lane * 8;
        ((float4*)o)[0] = make_float4(r[0], r[1], r[2], r[3]);
        ((float4*)o)[1] = make_float4(r[4], r[5], r[6], r[7]);
    }
}

// ---------------- launch ----------------
extern "C" void kernel_launch(void* const* d_in, const int* in_sizes, int n_in,
                              void* d_out, int out_size) {
    const float* xm  = (const float*)d_in[0];
    const float* xt  = (const float*)d_in[1];
    const int*   src = (const int*)d_in[2];
    const int*   dst = (const int*)d_in[3];
    const float* W1  = (const float*)d_in[4];
    const float* a1l = (const float*)d_in[5];
    const float* a1r = (const float*)d_in[6];
    const float* b1  = (const float*)d_in[7];
    const float* W2  = (const float*)d_in[8];
    const float* a2l = (const float*)d_in[9];
    const float* a2r = (const float*)d_in[10];
    const float* b2  = (const float*)d_in[11];
    float* out = (float*)d_out;

    cudaFuncSetAttribute(k_gemm_mma, cudaFuncAttributeMaxDynamicSharedMemorySize, GSM3);

    const int SB = (NP * 64 + 255) / 256;
    dim3 ggrid(NP / 128, 2, 4);
    const int PB = 1600;
    const int AB = (NN * 32 + 255) / 256;

    // GEMM placed at the profiled launch slot (4th kernel)
    k_prep<<<2048, 256>>>(W1, W2);
    k_split<<<SB, 256>>>(xm, 0);
    k_split<<<SB, 256>>>(xt, 1);
    k_gemm_mma<<<ggrid, 256, GSM3>>>(0, a1l, a1r);     // <- ncu slot

    k_zero<<<(4 * NN + 255) / 256, 256>>>();
    k_hist<<<(4 * EE + 255) / 256, 256>>>(dst);
    k_scan<<<4, 1024>>>();
    k_scatter<<<(4 * EE + 255) / 256, 256>>>(src, dst);
    k_u<<<128, 256>>>(W1, a1l, a1r, W2, a2l, a2r);

    // fix er for cross-type relations (dst type != src type)
    k_proj<<<PB, 256>>>(xt, 0, 0, 0, 1);   // er rel0: dst=xt
    k_proj<<<PB, 256>>>(xm, 0, 0, 3, 1);   // er rel3: dst=xm

    k_agg<<<AB, 256>>>(0, b1 + 0,   nullptr, 0);   // ht + split slot1
    k_agg<<<AB, 256>>>(1, b1 + 256, nullptr, 1);   // hm  = elu/3
    k_agg<<<AB, 256>>>(2, b1 + 512, nullptr, 2);   // hm += elu/3
    k_agg<<<AB, 256>>>(3, b1 + 768, nullptr, 3);   // hm += elu/3 + split slot0

    // ---- layer 2 ----
    k_gemm_mma<<<ggrid, 256, GSM3>>>(1, a2l, a2r);
    k_proj<<<PB, 256>>>(nullptr, 2, 1, 0, 1);  // er rel0: dst=ht
    k_proj<<<PB, 256>>>(nullptr, 1, 1, 3, 1);  // er rel3: dst=hm
    k_agg<<<AB, 256>>>(0, b2 + 0,   out + 0,   4);
    k_agg<<<AB, 256>>>(1, b2 + 256, out + 256, 4);
    k_agg<<<AB, 256>>>(2, b2 + 512, out + 512, 4);
    k_agg<<<AB, 256>>>(3, b2 + 768, out + 768, 4);
}

// round 17
// speedup vs baseline: 2.1895x; 1.0642x over previous
#include <cuda_runtime.h>
#include <cuda_bf16.h>
#include <cuda_fp16.h>
#include <math.h>
#include <stdint.h>

#define NN 50000
#define EE 500000
#define NP 50048   // NN padded to multiple of 128 for GEMM tiles
#define H 8

// ---------------- scratch (device globals; no runtime allocation) ----------------
__device__ __align__(16) __half g_f[4][(size_t)NP * 256];  // per-relation projected features (fp16)
__device__ float g_ht[(size_t)NP * 256];     // layer-1 tobacco features (elu applied)
__device__ float g_hm[(size_t)NP * 256];     // layer-1 merchant features (mean of 3, elu)
__device__ float g_el[4][NN * H];
__device__ float g_er[4][NN * H];
__device__ float g_U[2][4][2][256 * H];
__device__ __align__(16) __nv_bfloat16 g_Ah[2][(size_t)NP * 256];  // A hi (slot0: xm/hm, 1: xt/ht)
__device__ __align__(16) __nv_bfloat16 g_Al[2][(size_t)NP * 256];  // A lo
__device__ __align__(16) __nv_bfloat16 g_Bh16[8][256 * 256];       // W transposed [n][k], hi
__device__ __align__(16) __nv_bfloat16 g_Bl16[8][256 * 256];       // lo
__device__ int   g_rowptr[4][NN + 1];
__device__ int   g_wptr[4][NN];
__device__ int   g_cnt[4][NN];
__device__ int   g_bsum[4][64];
__device__ int   g_col[4][EE];

// ---------------- helpers ----------------
__device__ __forceinline__ uint32_t smem_u32(const void* p) {
    uint32_t a;
    asm("{ .reg .u64 t; cvta.to.shared.u64 t, %1; cvt.u32.u64 %0, t; }" : "=r"(a) : "l"(p));
    return a;
}
__device__ __forceinline__ void cp16(uint32_t saddr, const void* g) {
    asm volatile("cp.async.cg.shared.global [%0], [%1], 16;" :: "r"(saddr), "l"(g) : "memory");
}
__device__ __forceinline__ void ldm_x4(uint32_t* r, uint32_t a) {
    asm volatile("ldmatrix.sync.aligned.m8n8.x4.shared.b16 {%0,%1,%2,%3}, [%4];"
                 : "=r"(r[0]), "=r"(r[1]), "=r"(r[2]), "=r"(r[3]) : "r"(a));
}
__device__ __forceinline__ void ldm_x2(uint32_t* r, uint32_t a) {
    asm volatile("ldmatrix.sync.aligned.m8n8.x2.shared.b16 {%0,%1}, [%2];"
                 : "=r"(r[0]), "=r"(r[1]) : "r"(a));
}
__device__ __forceinline__ void mma_bf16(float* d, const uint32_t* a, const uint32_t* b) {
    asm volatile(
        "mma.sync.aligned.m16n8k16.row.col.f32.bf16.bf16.f32 "
        "{%0,%1,%2,%3}, {%4,%5,%6,%7}, {%8,%9}, {%0,%1,%2,%3};"
        : "+f"(d[0]), "+f"(d[1]), "+f"(d[2]), "+f"(d[3])
        : "r"(a[0]), "r"(a[1]), "r"(a[2]), "r"(a[3]), "r"(b[0]), "r"(b[1]));
}

// ---------------- init: zero CSR counters ----------------
__global__ void k_zero() {
    int i = blockIdx.x * blockDim.x + threadIdx.x;
    if (i < 4 * NN) ((int*)g_cnt)[i] = 0;
}

// ---------------- CSR build ----------------
__global__ void k_hist(const int* __restrict__ dst) {
    int i = blockIdx.x * blockDim.x + threadIdx.x;
    if (i >= 4 * EE) return;
    int rel = i / EE;
    atomicAdd(&g_cnt[rel][dst[i]], 1);
}

// 3-phase parallel scan over g_cnt -> exclusive g_rowptr/g_wptr
__global__ void k_scan1() {   // grid (49,4) x 1024: block-level inclusive scan
    int rel = blockIdx.y;
    int b = blockIdx.x;
    int tid = threadIdx.x;
    int l = tid & 31, w = tid >> 5;
    int i = b * 1024 + tid;
    int v = (i < NN) ? g_cnt[rel][i] : 0;
    int x = v;
#pragma unroll
    for (int off = 1; off < 32; off <<= 1) {
        int t = __shfl_up_sync(0xffffffffu, x, off);
        if (l >= off) x += t;
    }
    __shared__ int ws[32];
    if (l == 31) ws[w] = x;
    __syncthreads();
    if (w == 0) {
        int y = ws[l];
#pragma unroll
        for (int off = 1; off < 32; off <<= 1) {
            int t = __shfl_up_sync(0xffffffffu, y, off);
            if (l >= off) y += t;
        }
        ws[l] = y;
    }
    __syncthreads();
    int incl = x + (w ? ws[w - 1] : 0);
    if (i < NN) g_wptr[rel][i] = incl;          // temp: inclusive within block
    if (tid == 1023) g_bsum[rel][b] = incl;
}

__global__ void k_scan2() {   // 1 block of 4 threads: scan block sums per relation
    int rel = threadIdx.x;
    if (rel >= 4) return;
    int run = 0;
    for (int b = 0; b < 49; b++) {
        int t = g_bsum[rel][b];
        g_bsum[rel][b] = run;
        run += t;
    }
    g_rowptr[rel][NN] = run;
}

__global__ void k_scan3() {   // apply offsets -> exclusive rowptr/wptr
    int rel = blockIdx.y;
    int b = blockIdx.x;
    int i = b * 1024 + threadIdx.x;
    if (i >= NN) return;
    int excl = g_bsum[rel][b] + g_wptr[rel][i] - g_cnt[rel][i];
    g_rowptr[rel][i] = excl;
    g_wptr[rel][i] = excl;
}

__global__ void k_scatter(const int* __restrict__ src, const int* __restrict__ dst) {
    int i = blockIdx.x * blockDim.x + threadIdx.x;
    if (i >= 4 * EE) return;
    int rel = i / EE;
    int d = dst[i];
    int pos = atomicAdd(&g_wptr[rel][d], 1);
    g_col[rel][pos] = src[i];
}

// ---------------- U = per-head contraction of W with a ----------------
__global__ void k_u(const float* __restrict__ W1, const float* __restrict__ a1l,
                    const float* __restrict__ a1r, const float* __restrict__ W2,
                    const float* __restrict__ a2l, const float* __restrict__ a2r) {
    int i = blockIdx.x * blockDim.x + threadIdx.x;
    if (i >= 32768) return;
    int h = i & 7;
    int c = (i >> 3) & 255;
    int side = (i >> 11) & 1;
    int rel = (i >> 12) & 3;
    int layer = (i >> 14) & 1;
    const float* W = (layer ? W2 : W1) + (size_t)rel * 65536 + (size_t)c * 256 + h * 32;
    const float* a = (layer ? (side ? a2r : a2l) : (side ? a1r : a1l)) + (size_t)rel * 256 + h * 32;
    float s = 0.f;
#pragma unroll
    for (int d = 0; d < 32; d++) s += W[d] * a[d];
    g_U[layer][rel][side][c * 8 + h] = s;
}

// ---------------- prep: transpose W, split to bf16 hi/lo ----------------
__global__ void k_prep(const float* __restrict__ W1, const float* __restrict__ W2) {
    int i = blockIdx.x * blockDim.x + threadIdx.x;
    if (i >= 8 * 65536) return;
    int g = i >> 16;
    int rem = i & 65535;
    int n = rem >> 8;
    int k = rem & 255;
    const float* W = (g >= 4 ? W2 : W1) + (size_t)(g & 3) * 65536;
    float w = W[(size_t)k * 256 + n];
    __nv_bfloat16 hi = __float2bfloat16_rn(w);
    float lo = w - __bfloat162float(hi);
    g_Bh16[g][n * 256 + k] = hi;
    g_Bl16[g][n * 256 + k] = __float2bfloat16_rn(lo);
}

// ---------------- split A matrices into bf16 hi/lo (zero-pads rows NN..NP) ----------------
__global__ void k_split(const float* __restrict__ Xin, int slot) {
    size_t i = (size_t)blockIdx.x * blockDim.x + threadIdx.x;   // quad index
    if (i >= (size_t)NP * 64) return;
    size_t e = i * 4;
    int row = (int)(e >> 8);
    float4 v = make_float4(0.f, 0.f, 0.f, 0.f);
    if (row < NN) v = *(const float4*)(Xin + e);
    __nv_bfloat16 h0 = __float2bfloat16_rn(v.x), h1 = __float2bfloat16_rn(v.y);
    __nv_bfloat16 h2 = __float2bfloat16_rn(v.z), h3 = __float2bfloat16_rn(v.w);
    __nv_bfloat16 l0 = __float2bfloat16_rn(v.x - __bfloat162float(h0));
    __nv_bfloat16 l1 = __float2bfloat16_rn(v.y - __bfloat162float(h1));
    __nv_bfloat16 l2 = __float2bfloat16_rn(v.z - __bfloat162float(h2));
    __nv_bfloat16 l3 = __float2bfloat16_rn(v.w - __bfloat162float(h3));
    __nv_bfloat162 hh0, hh1, ll0, ll1;
    hh0.x = h0; hh0.y = h1; hh1.x = h2; hh1.y = h3;
    ll0.x = l0; ll0.y = l1; ll1.x = l2; ll1.y = l3;
    *(__nv_bfloat162*)(&g_Ah[slot][e]) = hh0;
    *(__nv_bfloat162*)(&g_Ah[slot][e + 2]) = hh1;
    *(__nv_bfloat162*)(&g_Al[slot][e]) = ll0;
    *(__nv_bfloat162*)(&g_Al[slot][e + 2]) = ll1;
}

// ---------------- mma.sync bf16 3-pass GEMM + fused el/er epilogue ----------------
// CTA tile 128x128, 8 warps of 64x32, K chunked by 32, paired-row smem layout,
// 3 stages, 2 CTAs/SM, single __syncthreads per chunk.
#define PRB   144
#define ABUF3 9216
#define STG3  (4 * ABUF3)     // 36864
#define GSM3  (3 * STG3)      // 110592

__device__ __forceinline__ uint32_t raddr(int r) {
    return (uint32_t)((r >> 1) * PRB + (r & 1) * 64);
}

__device__ __forceinline__ void gemm_issue3(
    char* smbase, int stage, int c, int tid,
    const __nv_bfloat16* __restrict__ Ah, const __nv_bfloat16* __restrict__ Al,
    const __nv_bfloat16* __restrict__ Bh, const __nv_bfloat16* __restrict__ Bl,
    int rowBase, int colBase)
{
    int kb = c * 32;
    uint32_t s = smem_u32(smbase + stage * STG3);
#pragma unroll
    for (int j = 0; j < 8; j++) {
        int mat = j >> 1;
        int idx = ((j & 1) << 8) + tid;   // 0..511
        int r = idx >> 2;                 // 0..127
        int q = idx & 3;                  // 16B chunk within 64B row
        uint32_t so = s + mat * ABUF3 + raddr(r) + q * 16;
        if (mat < 2) {
            size_t go = (size_t)(rowBase + r) * 256 + kb + q * 8;
            cp16(so, (mat == 0 ? Ah : Al) + go);
        } else {
            size_t go = (size_t)(colBase + r) * 256 + kb + q * 8;
            cp16(so, (mat == 2 ? Bh : Bl) + go);
        }
    }
    asm volatile("cp.async.commit_group;" ::: "memory");
}

__global__ void __launch_bounds__(256, 2) k_gemm_mma(
    int layer, const float* __restrict__ alw, const float* __restrict__ arw)
{
    extern __shared__ __align__(128) char sm[];
    const int tid = threadIdx.x;
    const int wid = tid >> 5;
    const int l = tid & 31;
    const int rel = blockIdx.z;
    const int rowBase = blockIdx.x * 128;
    const int colBase = blockIdx.y * 128;
    const int g = layer * 4 + rel;
    const int slot = (rel < 3) ? 0 : 1;

    const __nv_bfloat16* __restrict__ Ah = g_Ah[slot];
    const __nv_bfloat16* __restrict__ Al = g_Al[slot];
    const __nv_bfloat16* __restrict__ Bh = g_Bh16[g];
    const __nv_bfloat16* __restrict__ Bl = g_Bl16[g];
    __half* __restrict__ C = g_f[rel];

    const int mBase = (wid & 1) * 64;
    const int nBase = (wid >> 1) * 32;

    float acc[4][4][4];
#pragma unroll
    for (int mt = 0; mt < 4; mt++)
#pragma unroll
        for (int nt = 0; nt < 4; nt++)
#pragma unroll
            for (int q = 0; q < 4; q++) acc[mt][nt][q] = 0.f;

    gemm_issue3(sm, 0, 0, tid, Ah, Al, Bh, Bl, rowBase, colBase);
    gemm_issue3(sm, 1, 1, tid, Ah, Al, Bh, Bl, rowBase, colBase);

    // per-lane ldmatrix offsets (paired-row layout)
    const uint32_t aOff = raddr(mBase + (l & 15)) + ((l >> 4) << 4);
    const uint32_t bOff = raddr(nBase + (l & 7)) + (((l >> 3) & 1) << 4);

#pragma unroll 1
    for (int c = 0; c < 8; c++) {
        if (c < 7) asm volatile("cp.async.wait_group 1;" ::: "memory");
        else       asm volatile("cp.async.wait_group 0;" ::: "memory");
        __syncthreads();
        if (c < 6) {
            int stW = (c + 2) % 3;
            gemm_issue3(sm, stW, c + 2, tid, Ah, Al, Bh, Bl, rowBase, colBase);
        }

        uint32_t s = smem_u32(sm + (c % 3) * STG3);
#pragma unroll
        for (int kk = 0; kk < 2; kk++) {
            uint32_t ah[4][4], al2[4][4], bh[4][2], bl[4][2];
#pragma unroll
            for (int mt = 0; mt < 4; mt++) {
                uint32_t a = s + aOff + mt * (8 * PRB) + kk * 32;   // 16 rows = 8 pairs
                ldm_x4(ah[mt], a);
                ldm_x4(al2[mt], a + ABUF3);
            }
#pragma unroll
            for (int nt = 0; nt < 4; nt++) {
                uint32_t a = s + 2 * ABUF3 + bOff + nt * (4 * PRB) + kk * 32;  // 8 rows = 4 pairs
                ldm_x2(bh[nt], a);
                ldm_x2(bl[nt], a + ABUF3);
            }
#pragma unroll
            for (int mt = 0; mt < 4; mt++)
#pragma unroll
                for (int nt = 0; nt < 4; nt++) {
                    mma_bf16(acc[mt][nt], ah[mt], bh[nt]);
                    mma_bf16(acc[mt][nt], ah[mt], bl[nt]);
                    mma_bf16(acc[mt][nt], al2[mt], bh[nt]);
                }
        }
    }

    // ---- epilogue 1: write fp16 C tile ----
#pragma unroll
    for (int mt = 0; mt < 4; mt++) {
        int r0 = rowBase + mBase + mt * 16 + (l >> 2);
#pragma unroll
        for (int nt = 0; nt < 4; nt++) {
            int cc = colBase + nBase + nt * 8 + ((l & 3) << 1);
            __half* p = C + (size_t)r0 * 256 + cc;
            *(__half2*)p = __floats2half2_rn(acc[mt][nt][0], acc[mt][nt][1]);
            *(__half2*)(p + 8 * 256) = __floats2half2_rn(acc[mt][nt][2], acc[mt][nt][3]);
        }
    }

    // ---- epilogue 2: fused attention projections el/er (fp32 accumulators) ----
    {
        int h = (colBase >> 5) + (wid >> 1);
        const float* alp = alw + rel * 256 + h * 32;
        const float* arp = arw + rel * 256 + h * 32;
        float2 wl[4], wr[4];
#pragma unroll
        for (int nt = 0; nt < 4; nt++) {
            int d = nt * 8 + ((l & 3) << 1);
            wl[nt] = *(const float2*)(alp + d);
            wr[nt] = *(const float2*)(arp + d);
        }
#pragma unroll
        for (int mt = 0; mt < 4; mt++) {
            float elA = 0.f, erA = 0.f, elB = 0.f, erB = 0.f;
#pragma unroll
            for (int nt = 0; nt < 4; nt++) {
                elA += acc[mt][nt][0] * wl[nt].x + acc[mt][nt][1] * wl[nt].y;
                erA += acc[mt][nt][0] * wr[nt].x + acc[mt][nt][1] * wr[nt].y;
                elB += acc[mt][nt][2] * wl[nt].x + acc[mt][nt][3] * wl[nt].y;
                erB += acc[mt][nt][2] * wr[nt].x + acc[mt][nt][3] * wr[nt].y;
            }
#pragma unroll
            for (int off = 1; off <= 2; off <<= 1) {
                elA += __shfl_xor_sync(0xffffffffu, elA, off);
                erA += __shfl_xor_sync(0xffffffffu, erA, off);
                elB += __shfl_xor_sync(0xffffffffu, elB, off);
                erB += __shfl_xor_sync(0xffffffffu, erB, off);
            }
            if ((l & 3) == 0) {
                int rA = rowBase + mBase + mt * 16 + (l >> 2);
                int rB = rA + 8;
                if (rA < NN) { g_el[rel][rA * 8 + h] = elA; g_er[rel][rA * 8 + h] = erA; }
                if (rB < NN) { g_el[rel][rB * 8 + h] = elB; g_er[rel][rB * 8 + h] = erB; }
            }
        }
    }
}

// ---------------- small projection (only er for rel0/rel3): out[N,8] = X @ U ----------------
__global__ void k_proj(const float* __restrict__ Xin, int xsel, int layer, int rel, int side) {
    const float* __restrict__ X = (xsel == 0) ? Xin : ((xsel == 1) ? g_hm : g_ht);
    __shared__ float sU[256 * 9];
    const float* U = g_U[layer][rel][side];
    for (int i = threadIdx.x; i < 2048; i += blockDim.x) {
        int c = i >> 3, h = i & 7;
        sU[c * 9 + h] = U[i];
    }
    __syncthreads();
    float* out = side ? g_er[rel] : g_el[rel];
    int lane = threadIdx.x & 31;
    int warp = (blockIdx.x * blockDim.x + threadIdx.x) >> 5;
    int nw = (gridDim.x * blockDim.x) >> 5;
    for (int row = warp; row < NN; row += nw) {
        float acc[8] = {0, 0, 0, 0, 0, 0, 0, 0};
#pragma unroll
        for (int i = 0; i < 8; i++) {
            float x = X[(size_t)row * 256 + i * 32 + lane];
            const float* u = &sU[(i * 32 + lane) * 9];
#pragma unroll
            for (int h = 0; h < 8; h++) acc[h] += x * u[h];
        }
#pragma unroll
        for (int h = 0; h < 8; h++) {
#pragma unroll
            for (int off = 16; off; off >>= 1) acc[h] += __shfl_xor_sync(0xffffffffu, acc[h], off);
        }
        if (lane == 0) {
#pragma unroll
            for (int h = 0; h < 8; h++) out[(size_t)row * 8 + h] = acc[h];
        }
    }
}

// ---------------- GAT edge softmax + aggregation (warp per dst node) ----------------
// mode 0: store elu -> g_ht AND bf16 hi/lo split to slot 1   (layer1 rel0)
// mode 1: g_hm  = elu/3                                      (layer1 rel1)
// mode 2: g_hm += elu/3                                      (layer1 rel2)
// mode 3: g_hm += elu/3, store final, split to slot 0        (layer1 rel3)
// mode 4: store elu -> out_ext (stride 1024)                 (layer2)
__global__ void k_agg(int rel, const float* __restrict__ bias,
                      float* __restrict__ out_ext, int mode) {
    int gw = (blockIdx.x * blockDim.x + threadIdx.x) >> 5;
    if (gw >= NN) return;
    int lane = threadIdx.x & 31;
    int h = lane >> 2;
    const __half* __restrict__ f = g_f[rel];
    const int* __restrict__ col = g_col[rel];
    const float* __restrict__ el = g_el[rel];
    int beg = g_rowptr[rel][gw];
    int end = g_rowptr[rel][gw + 1];
    float erd = g_er[rel][gw * H + h];

    float m = -1e30f;
    for (int j = beg; j < end; j++) {
        int s = col[j];
        float e = el[s * H + h] + erd;
        e = (e > 0.f) ? e : 0.2f * e;
        m = fmaxf(m, e);
    }
    float acc[8];
#pragma unroll
    for (int k = 0; k < 8; k++) acc[k] = 0.f;
    float den = 0.f;
    for (int j = beg; j < end; j++) {
        int s = col[j];
        float e = el[s * H + h] + erd;
        e = (e > 0.f) ? e : 0.2f * e;
        float ex = __expf(e - m);
        den += ex;
        uint4 raw = *(const uint4*)(f + (size_t)s * 256 + lane * 8);
        float2 f0 = __half22float2(*(__half2*)&raw.x);
        float2 f1 = __half22float2(*(__half2*)&raw.y);
        float2 f2 = __half22float2(*(__half2*)&raw.z);
        float2 f3 = __half22float2(*(__half2*)&raw.w);
        acc[0] += ex * f0.x; acc[1] += ex * f0.y; acc[2] += ex * f1.x; acc[3] += ex * f1.y;
        acc[4] += ex * f2.x; acc[5] += ex * f2.y; acc[6] += ex * f3.x; acc[7] += ex * f3.y;
    }
    float inv = (den > 0.f) ? 1.f / den : 0.f;
    float r[8];
#pragma unroll
    for (int k = 0; k < 8; k++) {
        float v = acc[k] * inv + bias[lane * 8 + k];
        r[k] = (v > 0.f) ? v : expm1f(v);
    }
    if (mode == 0) {
        float* o = g_ht + (size_t)gw * 256 + lane * 8;
        ((float4*)o)[0] = make_float4(r[0], r[1], r[2], r[3]);
        ((float4*)o)[1] = make_float4(r[4], r[5], r[6], r[7]);
        __align__(16) __nv_bfloat16 hi[8], lo[8];
#pragma unroll
        for (int k = 0; k < 8; k++) {
            hi[k] = __float2bfloat16_rn(r[k]);
            lo[k] = __float2bfloat16_rn(r[k] - __bfloat162float(hi[k]));
        }
        *(uint4*)(&g_Ah[1][(size_t)gw * 256 + lane * 8]) = *(uint4*)hi;
        *(uint4*)(&g_Al[1][(size_t)gw * 256 + lane * 8]) = *(uint4*)lo;
    } else if (mode == 1) {
        float* o = g_hm + (size_t)gw * 256 + lane * 8;
        const float third = 1.f / 3.f;
        ((float4*)o)[0] = make_float4(r[0] * third, r[1] * third, r[2] * third, r[3] * third);
        ((float4*)o)[1] = make_float4(r[4] * third, r[5] * third, r[6] * third, r[7] * third);
    } else if (mode == 2 || mode == 3) {
        float* o = g_hm + (size_t)gw * 256 + lane * 8;
        float4 c0 = ((float4*)o)[0], c1 = ((float4*)o)[1];
        const float third = 1.f / 3.f;
        c0.x += r[0] * third; c0.y += r[1] * third; c0.z += r[2] * third; c0.w += r[3] * third;
        c1.x += r[4] * third; c1.y += r[5] * third; c1.z += r[6] * third; c1.w += r[7] * third;
        ((float4*)o)[0] = c0;
        ((float4*)o)[1] = c1;
        if (mode == 3) {
            float fin[8] = {c0.x, c0.y, c0.z, c0.w, c1.x, c1.y, c1.z, c1.w};
            __align__(16) __nv_bfloat16 hi[8], lo[8];
#pragma unroll
            for (int k = 0; k < 8; k++) {
                hi[k] = __float2bfloat16_rn(fin[k]);
                lo[k] = __float2bfloat16_rn(fin[k] - __bfloat162float(hi[k]));
            }
            *(uint4*)(&g_Ah[0][(size_t)gw * 256 + lane * 8]) = *(uint4*)hi;
            *(uint4*)(&g_Al[0][(size_t)gw * 256 + lane * 8]) = *(uint4*)lo;
        }
    } else {
        float* o = out_ext + (size_t)gw * 1024 + lane * 8;
        ((float4*)o)[0] = make_float4(r[0], r[1], r[2], r[3]);
        ((float4*)o)[1] = make_float4(r[4], r[5], r[6], r[7]);
    }
}

// ---------------- launch ----------------
extern "C" void kernel_launch(void* const* d_in, const int* in_sizes, int n_in,
                              void* d_out, int out_size) {
    const float* xm  = (const float*)d_in[0];
    const float* xt  = (const float*)d_in[1];
    const int*   src = (const int*)d_in[2];
    const int*   dst = (const int*)d_in[3];
    const float* W1  = (const float*)d_in[4];
    const float* a1l = (const float*)d_in[5];
    const float* a1r = (const float*)d_in[6];
    const float* b1  = (const float*)d_in[7];
    const float* W2  = (const float*)d_in[8];
    const float* a2l = (const float*)d_in[9];
    const float* a2r = (const float*)d_in[10];
    const float* b2  = (const float*)d_in[11];
    float* out = (float*)d_out;

    cudaFuncSetAttribute(k_gemm_mma, cudaFuncAttributeMaxDynamicSharedMemorySize, GSM3);

    const int SB = (NP * 64 + 255) / 256;
    dim3 ggrid(NP / 128, 2, 4);
    const int PB = 1600;
    const int AB = (NN * 32 + 255) / 256;
    dim3 sgrid(49, 4);

    // GEMM placed at the profiled launch slot (4th kernel)
    k_prep<<<2048, 256>>>(W1, W2);
    k_split<<<SB, 256>>>(xm, 0);
    k_split<<<SB, 256>>>(xt, 1);
    k_gemm_mma<<<ggrid, 256, GSM3>>>(0, a1l, a1r);     // <- ncu slot

    k_zero<<<(4 * NN + 255) / 256, 256>>>();
    k_hist<<<(4 * EE + 255) / 256, 256>>>(dst);
    k_scan1<<<sgrid, 1024>>>();
    k_scan2<<<1, 4>>>();
    k_scan3<<<sgrid, 1024>>>();
    k_scatter<<<(4 * EE + 255) / 256, 256>>>(src, dst);
    k_u<<<128, 256>>>(W1, a1l, a1r, W2, a2l, a2r);

    // fix er for cross-type relations (dst type != src type)
    k_proj<<<PB, 256>>>(xt, 0, 0, 0, 1);   // er rel0: dst=xt
    k_proj<<<PB, 256>>>(xm, 0, 0, 3, 1);   // er rel3: dst=xm

    k_agg<<<AB, 256>>>(0, b1 + 0,   nullptr, 0);   // ht + split slot1
    k_agg<<<AB, 256>>>(1, b1 + 256, nullptr, 1);   // hm  = elu/3
    k_agg<<<AB, 256>>>(2, b1 + 512, nullptr, 2);   // hm += elu/3
    k_agg<<<AB, 256>>>(3, b1 + 768, nullptr, 3);   // hm += elu/3 + split slot0

    // ---- layer 2 ----
    k_gemm_mma<<<ggrid, 256, GSM3>>>(1, a2l, a2r);
    k_proj<<<PB, 256>>>(nullptr, 2, 1, 0, 1);  // er rel0: dst=ht
    k_proj<<<PB, 256>>>(nullptr, 1, 1, 3, 1);  // er rel3: dst=hm
    k_agg<<<AB, 256>>>(0, b2 + 0,   out + 0,   4);
    k_agg<<<AB, 256>>>(1, b2 + 256, out + 256, 4);
    k_agg<<<AB, 256>>>(2, b2 + 512, out + 512, 4);
    k_agg<<<AB, 256>>>(3, b2 + 768, out + 768, 4);
}